// round 5
// baseline (speedup 1.0000x reference)
#include <cuda_runtime.h>
#include <math.h>

#define BSZ 4
#define SEQ 1024
#define VOC 32000
#define DM 1024
#define CC 16
#define DC 64
#define NBK 8
#define MS 64
#define EE 128
#define NR (BSZ*SEQ)
#define LOGN ((long long)NR*VOC)

// ---------------- scratch (device globals: the sanctioned no-alloc path) ----
__device__ float g_X[NR*DM];           // x_col, later: integrated / stage3 H
__device__ float g_H[NR*DM];           // stage1 H (modulated after PCM)
__device__ float g_bufZ[NR*CC*EE];     // z then h ; later reused as cum_em
__device__ float g_bufA[NR*CC*EE];     // gate a
__device__ float g_surp[NR*DM];        // surprise, then in-place cumsum S
__device__ float g_seed[NR*DM];
__device__ float g_wc[NR*DM];
__device__ float g_pms[NR*DM];         // sum_b sigmoid(pm_state + cum_pm)
__device__ float g_lno[NR*DM];
__device__ float g_dpm[(long long)NBK*NR*DM];
__device__ float g_q[(long long)BSZ*NBK*SEQ*DM];
__device__ float g_sim[(long long)BSZ*NBK*SEQ*MS];
__device__ float g_wnv[NR*NBK];
__device__ float g_smg[NR];
__device__ float g_nvs[NR];
__device__ float g_wiv[NR];
__device__ float g_kiv[BSZ*NBK*MS];
__device__ float g_aux[2048];

__device__ __forceinline__ float sigm(float x){ return 1.f/(1.f+expf(-x)); }

__device__ __forceinline__ float blockSum256(float v, float* sred){
    __syncthreads();
    int lane = threadIdx.x & 31, w = threadIdx.x >> 5;
    #pragma unroll
    for (int o=16;o;o>>=1) v += __shfl_xor_sync(0xffffffffu, v, o);
    if (lane==0) sred[w]=v;
    __syncthreads();
    float t = (threadIdx.x<8)? sred[threadIdx.x] : 0.f;
    if (w==0){
        #pragma unroll
        for (int o=4;o;o>>=1) t += __shfl_xor_sync(0xffffffffu, t, o);
        if (lane==0) sred[0]=t;
    }
    __syncthreads();
    return sred[0];
}

// ---------------- generic batched 128x128x8 SGEMM ---------------------------
// C[z] = alpha * A[z/zdivA] * op(B[z]).  TB: B row-major [Ncols,K] (B^T).
// M%128==0, K%8==0, lda/ldb multiples of 4. Ncols guarded.
template<bool TB>
__global__ void __launch_bounds__(256,2)
sgemm_k(const float* __restrict__ Ag, const float* __restrict__ Bg, float* __restrict__ Cg,
        int M, int Ncols, int K, int lda, int ldb, int ldc,
        long long sA, long long sB, long long sC, int zdivA, float alpha)
{
    __shared__ float As[2][8][128];
    __shared__ float Bs[2][8][128];
    const int z = blockIdx.z;
    const float* A = Ag + (long long)(z/zdivA)*sA;
    const float* B = Bg + (long long)z*sB;
    float* C = Cg + (long long)z*sC;
    const int m0 = blockIdx.y*128, n0 = blockIdx.x*128;
    const int tid = threadIdx.x;
    const int tx = tid & 15, ty = tid >> 4;
    const int arow = tid >> 1, akk = (tid & 1) << 2;
    const int nbrow = tid >> 5, nbn = (tid & 31) << 2;
    float acc[8][8];
    #pragma unroll
    for (int i=0;i<8;i++)
        #pragma unroll
        for (int j=0;j<8;j++) acc[i][j]=0.f;
    const int nk = K >> 3;

    auto fetchA = [&](int kb){
        return *reinterpret_cast<const float4*>(A + (long long)(m0+arow)*lda + kb + akk);
    };
    auto storeA = [&](float4 v, int bf){
        As[bf][akk+0][arow]=v.x; As[bf][akk+1][arow]=v.y;
        As[bf][akk+2][arow]=v.z; As[bf][akk+3][arow]=v.w;
    };
    auto fetchB = [&](int kb){
        float4 v = make_float4(0.f,0.f,0.f,0.f);
        if (TB){
            int nc = n0 + arow;
            if (nc < Ncols) v = *reinterpret_cast<const float4*>(B + (long long)nc*ldb + kb + akk);
        } else {
            v = *reinterpret_cast<const float4*>(B + (long long)(kb+nbrow)*ldb + n0 + nbn);
        }
        return v;
    };
    auto storeB = [&](float4 v, int bf){
        if (TB){
            Bs[bf][akk+0][arow]=v.x; Bs[bf][akk+1][arow]=v.y;
            Bs[bf][akk+2][arow]=v.z; Bs[bf][akk+3][arow]=v.w;
        } else {
            *reinterpret_cast<float4*>(&Bs[bf][nbrow][nbn]) = v;
        }
    };

    storeA(fetchA(0),0); storeB(fetchB(0),0);
    __syncthreads();
    for (int t=0;t<nk;t++){
        int bf = t & 1;
        float4 pa, pb;
        bool has = (t+1 < nk);
        if (has){ pa = fetchA((t+1)<<3); pb = fetchB((t+1)<<3); }
        #pragma unroll
        for (int kk=0;kk<8;kk++){
            float af[8], bfv[8];
            *reinterpret_cast<float4*>(&af[0]) = *reinterpret_cast<const float4*>(&As[bf][kk][ty<<2]);
            *reinterpret_cast<float4*>(&af[4]) = *reinterpret_cast<const float4*>(&As[bf][kk][64+(ty<<2)]);
            *reinterpret_cast<float4*>(&bfv[0]) = *reinterpret_cast<const float4*>(&Bs[bf][kk][tx<<2]);
            *reinterpret_cast<float4*>(&bfv[4]) = *reinterpret_cast<const float4*>(&Bs[bf][kk][64+(tx<<2)]);
            #pragma unroll
            for (int i=0;i<8;i++)
                #pragma unroll
                for (int j=0;j<8;j++) acc[i][j] = fmaf(af[i], bfv[j], acc[i][j]);
        }
        __syncthreads();
        if (has){ storeA(pa, bf^1); storeB(pb, bf^1); __syncthreads(); }
    }
    #pragma unroll
    for (int i=0;i<8;i++){
        int row = m0 + ((i<4)? (ty<<2)+i : 64+(ty<<2)+i-4);
        #pragma unroll
        for (int j=0;j<8;j++){
            int col = n0 + ((j<4)? (tx<<2)+j : 64+(tx<<2)+j-4);
            if (col < Ncols) C[(long long)row*ldc + col] = alpha*acc[i][j];
        }
    }
}

// ---------------- embedding -------------------------------------------------
__global__ void embed_k(const int* __restrict__ ids, const float* __restrict__ emb,
                        const float* __restrict__ pos, float* __restrict__ X, float* __restrict__ H)
{
    int r = blockIdx.x, n = r & (SEQ-1);
    const float* ep = emb + (long long)ids[r]*DM;
    const float* pp = pos + (long long)n*DM;
    for (int d = threadIdx.x; d < DM; d += 256){
        float v = ep[d] + pp[d];
        X[(long long)r*DM+d] = v; H[(long long)r*DM+d] = v;
    }
}

// ---------------- scan layer: LN + z/a projections --------------------------
__global__ void __launch_bounds__(256)
lnproj_k(const float* __restrict__ H, const float* __restrict__ Win, const float* __restrict__ Wg,
         const float* __restrict__ gam, const float* __restrict__ bet,
         float* __restrict__ bufZ, float* __restrict__ bufA)
{
    __shared__ float sX[32][64];
    __shared__ float sW[64*128];
    const int c = blockIdx.x, r0 = blockIdx.y*32, tid = threadIdx.x;
    for (int i=tid;i<32*64;i+=256){
        int row=i>>6, d=i&63;
        sX[row][d] = H[(((long long)(r0+row))*CC+c)*DC+d];
    }
    __syncthreads();
    const int w = tid>>5, lane = tid&31;
    for (int row=w; row<32; row+=8){
        float x0=sX[row][lane], x1=sX[row][lane+32];
        float sm=x0+x1;
        #pragma unroll
        for (int o=16;o;o>>=1) sm += __shfl_xor_sync(0xffffffffu, sm, o);
        float mu = sm*(1.f/64.f);
        float d0=x0-mu, d1=x1-mu;
        float vs=d0*d0+d1*d1;
        #pragma unroll
        for (int o=16;o;o>>=1) vs += __shfl_xor_sync(0xffffffffu, vs, o);
        float inv = rsqrtf(vs*(1.f/64.f)+1e-5f);
        sX[row][lane]    = d0*inv*gam[lane]   +bet[lane];
        sX[row][lane+32] = d1*inv*gam[lane+32]+bet[lane+32];
    }
    __syncthreads();
    for (int i=tid;i<64*128/4;i+=256)
        reinterpret_cast<float4*>(sW)[i] = reinterpret_cast<const float4*>(Win + c*64*128)[i];
    __syncthreads();
    for (int qd=tid; qd<1024; qd+=256){
        int row=qd>>5, e0=(qd&31)<<2;
        float4 a=make_float4(0,0,0,0);
        #pragma unroll 8
        for (int d=0;d<64;d++){
            float xv=sX[row][d];
            float4 wv=*reinterpret_cast<const float4*>(&sW[d*128+e0]);
            a.x=fmaf(xv,wv.x,a.x); a.y=fmaf(xv,wv.y,a.y); a.z=fmaf(xv,wv.z,a.z); a.w=fmaf(xv,wv.w,a.w);
        }
        *reinterpret_cast<float4*>(&bufZ[(((long long)(r0+row))*CC+c)*EE+e0]) = a;
    }
    __syncthreads();
    for (int i=tid;i<64*128/4;i+=256)
        reinterpret_cast<float4*>(sW)[i] = reinterpret_cast<const float4*>(Wg + c*64*128)[i];
    __syncthreads();
    for (int qd=tid; qd<1024; qd+=256){
        int row=qd>>5, e0=(qd&31)<<2;
        float4 a=make_float4(0,0,0,0);
        #pragma unroll 8
        for (int d=0;d<64;d++){
            float xv=sX[row][d];
            float4 wv=*reinterpret_cast<const float4*>(&sW[d*128+e0]);
            a.x=fmaf(xv,wv.x,a.x); a.y=fmaf(xv,wv.y,a.y); a.z=fmaf(xv,wv.z,a.z); a.w=fmaf(xv,wv.w,a.w);
        }
        a.x=sigm(a.x); a.y=sigm(a.y); a.z=sigm(a.z); a.w=sigm(a.w);
        *reinterpret_cast<float4*>(&bufA[(((long long)(r0+row))*CC+c)*EE+e0]) = a;
    }
}

// ---------------- gated recurrence over time --------------------------------
__global__ void scan_k(float* __restrict__ Z, const float* __restrict__ A)
{
    int ch = blockIdx.x*256 + threadIdx.x;   // BS*C*E = 8192 channels
    const int str = CC*EE;                    // 2048
    long long p = (long long)(ch>>11)*((long long)SEQ*str) + (ch & (str-1));
    float h = 0.f;
    for (int n=0;n<SEQ;n+=4){
        float z0=Z[p], z1=Z[p+str], z2=Z[p+2*str], z3=Z[p+3*str];
        float a0=A[p], a1=A[p+str], a2=A[p+2*str], a3=A[p+3*str];
        h = fmaf(a0, h-z0, z0); Z[p]=h;
        h = fmaf(a1, h-z1, z1); Z[p+str]=h;
        h = fmaf(a2, h-z2, z2); Z[p+2*str]=h;
        h = fmaf(a3, h-z3, z3); Z[p+3*str]=h;
        p += 4*str;
    }
}

// ---------------- scan output projection + residual -------------------------
__global__ void __launch_bounds__(256)
outproj_k(const float* __restrict__ hbuf, const float* __restrict__ Wout, float* __restrict__ H)
{
    __shared__ float sh[16][128];
    __shared__ float sW[128*64];
    const int c = blockIdx.x, r0 = blockIdx.y*16, tid = threadIdx.x;
    for (int i=tid;i<16*128/4;i+=256){
        int row=i>>5, e0=(i&31)<<2;
        *reinterpret_cast<float4*>(&sh[row][e0]) =
            *reinterpret_cast<const float4*>(&hbuf[(((long long)(r0+row))*CC+c)*EE+e0]);
    }
    for (int i=tid;i<128*64/4;i+=256)
        reinterpret_cast<float4*>(sW)[i] = reinterpret_cast<const float4*>(Wout + c*128*64)[i];
    __syncthreads();
    int row = tid>>4, d0 = (tid&15)<<2;
    float4 a=make_float4(0,0,0,0);
    #pragma unroll 8
    for (int e=0;e<128;e++){
        float hv=sh[row][e];
        float4 wv=*reinterpret_cast<const float4*>(&sW[e*64+d0]);
        a.x=fmaf(hv,wv.x,a.x); a.y=fmaf(hv,wv.y,a.y); a.z=fmaf(hv,wv.z,a.z); a.w=fmaf(hv,wv.w,a.w);
    }
    long long o = (((long long)(r0+row))*CC+c)*DC+d0;
    float4 h0 = *reinterpret_cast<const float4*>(&H[o]);
    a.x+=h0.x; a.y+=h0.y; a.z+=h0.z; a.w+=h0.w;
    *reinterpret_cast<float4*>(&H[o]) = a;
}

// ---------------- PCM: predict, surprise, modulate, aux partial -------------
__global__ void __launch_bounds__(256)
pcm_k(float* __restrict__ H, const float* __restrict__ X, const float* __restrict__ Wpred,
      float* __restrict__ surp, float* __restrict__ auxp)
{
    __shared__ float sH[32][64];
    __shared__ float sW[64*64];
    __shared__ float sred[32];
    const int c = blockIdx.x, r0 = blockIdx.y*32, tid = threadIdx.x;
    for (int i=tid;i<32*64;i+=256){
        int row=i>>6, d=i&63;
        sH[row][d] = H[(((long long)(r0+row))*CC+c)*DC+d];
    }
    for (int i=tid;i<64*64/4;i+=256)
        reinterpret_cast<float4*>(sW)[i] = reinterpret_cast<const float4*>(Wpred + c*64*64)[i];
    __syncthreads();
    float auxa = 0.f;
    for (int qd=tid; qd<512; qd+=256){
        int row=qd>>4, d0=(qd&15)<<2;
        float4 a=make_float4(0,0,0,0);
        #pragma unroll 8
        for (int d=0;d<64;d++){
            float hv=sH[row][d];
            float4 wv=*reinterpret_cast<const float4*>(&sW[d*64+d0]);
            a.x=fmaf(hv,wv.x,a.x); a.y=fmaf(hv,wv.y,a.y); a.z=fmaf(hv,wv.z,a.z); a.w=fmaf(hv,wv.w,a.w);
        }
        long long gi = (((long long)(r0+row))*CC+c)*DC+d0;
        float4 xv = *reinterpret_cast<const float4*>(&X[gi]);
        float dx=a.x-xv.x, dy=a.y-xv.y, dz=a.z-xv.z, dw=a.w-xv.w;
        auxa += dx*dx+dy*dy+dz*dz+dw*dw;
        float4 sp = make_float4(fabsf(dx),fabsf(dy),fabsf(dz),fabsf(dw));
        *reinterpret_cast<float4*>(&surp[gi]) = sp;
        float4 hn;
        hn.x = sH[row][d0+0]*(1.f+tanhf(sp.x));
        hn.y = sH[row][d0+1]*(1.f+tanhf(sp.y));
        hn.z = sH[row][d0+2]*(1.f+tanhf(sp.z));
        hn.w = sH[row][d0+3]*(1.f+tanhf(sp.w));
        *reinterpret_cast<float4*>(&H[gi]) = hn;
    }
    float tot = blockSum256(auxa, sred);
    if (tid==0) auxp[blockIdx.y*CC + c] = tot;
}

// ---------------- seed & w_cand projections ---------------------------------
__global__ void __launch_bounds__(256)
seedw_k(const float* __restrict__ H, const float* __restrict__ Ws, const float* __restrict__ Ww,
        float* __restrict__ seed, float* __restrict__ wc)
{
    __shared__ float sH[32][64];
    __shared__ float sWa[64*64];
    __shared__ float sWb[64*64];
    const int c = blockIdx.x, r0 = blockIdx.y*32, tid = threadIdx.x;
    for (int i=tid;i<32*64;i+=256){
        int row=i>>6, d=i&63;
        sH[row][d] = H[(((long long)(r0+row))*CC+c)*DC+d];
    }
    for (int i=tid;i<64*64/4;i+=256){
        reinterpret_cast<float4*>(sWa)[i] = reinterpret_cast<const float4*>(Ws + c*64*64)[i];
        reinterpret_cast<float4*>(sWb)[i] = reinterpret_cast<const float4*>(Ww + c*64*64)[i];
    }
    __syncthreads();
    for (int qd=tid; qd<512; qd+=256){
        int row=qd>>4, d0=(qd&15)<<2;
        float4 a=make_float4(0,0,0,0), b=make_float4(0,0,0,0);
        #pragma unroll 8
        for (int d=0;d<64;d++){
            float hv=sH[row][d];
            float4 wa=*reinterpret_cast<const float4*>(&sWa[d*64+d0]);
            float4 wb=*reinterpret_cast<const float4*>(&sWb[d*64+d0]);
            a.x=fmaf(hv,wa.x,a.x); a.y=fmaf(hv,wa.y,a.y); a.z=fmaf(hv,wa.z,a.z); a.w=fmaf(hv,wa.w,a.w);
            b.x=fmaf(hv,wb.x,b.x); b.y=fmaf(hv,wb.y,b.y); b.z=fmaf(hv,wb.z,b.z); b.w=fmaf(hv,wb.w,b.w);
        }
        long long gi = (((long long)(r0+row))*CC+c)*DC+d0;
        *reinterpret_cast<float4*>(&seed[gi]) = a;
        *reinterpret_cast<float4*>(&wc[gi]) = b;
    }
}

// ---------------- per-row stats: surp mean, wc norm, w_nov ------------------
__global__ void __launch_bounds__(256)
rowstat_k(const float* __restrict__ surp, const float* __restrict__ wc,
          const float* __restrict__ Hf, const float* __restrict__ Wnv,
          const float* __restrict__ Wnb, float* __restrict__ smg,
          float* __restrict__ wiv, float* __restrict__ wnv)
{
    __shared__ float sred[32];
    const int r = blockIdx.x, tid = threadIdx.x;
    long long base = (long long)r*DM + tid*4;
    float4 sv = *reinterpret_cast<const float4*>(surp + base);
    float4 wv = *reinterpret_cast<const float4*>(wc + base);
    float4 hv = *reinterpret_cast<const float4*>(Hf + base);
    float s1 = sv.x+sv.y+sv.z+sv.w;
    float s2 = wv.x*wv.x+wv.y*wv.y+wv.z*wv.z+wv.w*wv.w;
    float t1 = blockSum256(s1, sred);
    if (tid==0) smg[r] = sigm(t1*(1.f/(float)DM));
    float t2 = blockSum256(s2, sred);
    if (tid==0) wiv[r] = 1.f/(sqrtf(t2)+1e-6f);
    float acc[NBK];
    #pragma unroll
    for (int b=0;b<NBK;b++) acc[b]=0.f;
    float hvv[4] = {hv.x,hv.y,hv.z,hv.w};
    #pragma unroll
    for (int j=0;j<4;j++){
        const float* wr = Wnv + (tid*4+j)*NBK;
        #pragma unroll
        for (int b=0;b<NBK;b++) acc[b] = fmaf(hvv[j], wr[b], acc[b]);
    }
    #pragma unroll
    for (int b=0;b<NBK;b++){
        float t = blockSum256(acc[b], sred);
        if (tid==0) wnv[r*NBK+b] = sigm(t + Wnb[b]);
    }
}

// ---------------- em_K inverse norms ----------------------------------------
__global__ void knorm_k(const float* __restrict__ emK, float* __restrict__ kiv)
{
    __shared__ float sred[32];
    const int row = blockIdx.x;
    float4 v = *reinterpret_cast<const float4*>(emK + (long long)row*DM + threadIdx.x*4);
    float s = v.x*v.x+v.y*v.y+v.z*v.z+v.w*v.w;
    float t = blockSum256(s, sred);
    if (threadIdx.x==0) kiv[row] = 1.f/(sqrtf(t)+1e-6f);
}

// ---------------- in-place causal cumsum over time --------------------------
__global__ void cumsum_k(float* __restrict__ X)
{
    int ch = blockIdx.x*256 + threadIdx.x;   // BS*DM = 4096 channels
    long long p = (long long)(ch>>10)*((long long)SEQ*DM) + (ch & (DM-1));
    float h = 0.f;
    for (int n=0;n<SEQ;n+=4){
        float v0=X[p], v1=X[p+DM], v2=X[p+2*DM], v3=X[p+3*DM];
        h+=v0; X[p]=h; h+=v1; X[p+DM]=h; h+=v2; X[p+2*DM]=h; h+=v3; X[p+3*DM]=h;
        p += 4*DM;
    }
}

// ---------------- pm sigmoid-sum epilogue -----------------------------------
__global__ void pmsum_k(const float* __restrict__ dpm, const float* __restrict__ pmst,
                        float* __restrict__ pms)
{
    const int r = blockIdx.x, s = r >> 10;
    for (int d = threadIdx.x; d < DM; d += 256){
        float acc = 0.f;
        #pragma unroll
        for (int b=0;b<NBK;b++)
            acc += sigm(pmst[((long long)s*NBK+b)*DM+d] + dpm[((long long)b*NR + r)*DM + d]);
        pms[(long long)r*DM+d] = acc;
    }
}

// ---------------- novelty -> summed write gate ------------------------------
__global__ void novel_k(const float* __restrict__ sim, const float* __restrict__ wnv,
                        const float* __restrict__ smg, const float* __restrict__ wiv,
                        const float* __restrict__ kiv, float* __restrict__ nvs)
{
    __shared__ float snov[NBK];
    const int r = blockIdx.x, s = r >> 10, n = r & (SEQ-1);
    const int b = threadIdx.x >> 5, lane = threadIdx.x & 31;
    const int z = s*NBK + b;
    const float* sp = sim + ((long long)z*SEQ + n)*MS;
    const float* kp = kiv + z*MS;
    float m = fmaxf(sp[lane]*kp[lane], sp[lane+32]*kp[lane+32]);
    #pragma unroll
    for (int o=16;o;o>>=1) m = fmaxf(m, __shfl_xor_sync(0xffffffffu, m, o));
    if (lane==0){
        float msim = m * wiv[r];
        snov[b] = wnv[r*NBK+b] * smg[r] * fmaxf(0.f, 1.f - msim);
    }
    __syncthreads();
    if (threadIdx.x==0){
        float t=0.f;
        #pragma unroll
        for (int i=0;i<NBK;i++) t += snov[i];
        nvs[r] = t;
    }
}

__global__ void cem_k(const float* __restrict__ nvs, const float* __restrict__ wc,
                      float* __restrict__ cem)
{
    const int r = blockIdx.x;
    float nv = nvs[r];
    long long base = (long long)r*DM + threadIdx.x*4;
    float4 v = *reinterpret_cast<const float4*>(wc + base);
    v.x*=nv; v.y*=nv; v.z*=nv; v.w*=nv;
    *reinterpret_cast<float4*>(cem + base) = v;
}

// ---------------- trail attention pieces ------------------------------------
__global__ void qinit_k(const float* __restrict__ seed, float* __restrict__ q)
{
    long long f = (long long)blockIdx.x*256 + threadIdx.x;  // float4 index
    const long long per = (long long)SEQ*DM/4;              // 262144
    for (int it=0; it<4; it++, f += (long long)8192*256){
        long long z = f / per, rem = f - z*per;
        long long s = z >> 3;
        reinterpret_cast<float4*>(q)[f] =
            reinterpret_cast<const float4*>(seed)[s*per + rem];
    }
}

__global__ void softmax_k(float* __restrict__ sim)
{
    const int row = blockIdx.x*8 + (threadIdx.x>>5);  // 32768 rows
    const int lane = threadIdx.x & 31;
    float* p = sim + (long long)row*MS;
    const float scale = 0.03125f;  // 1/sqrt(1024)
    float a = p[lane]*scale, b = p[lane+32]*scale;
    float m = fmaxf(a,b);
    #pragma unroll
    for (int o=16;o;o>>=1) m = fmaxf(m, __shfl_xor_sync(0xffffffffu, m, o));
    float ea = expf(a-m), eb = expf(b-m);
    float s = ea+eb;
    #pragma unroll
    for (int o=16;o;o>>=1) s += __shfl_xor_sync(0xffffffffu, s, o);
    float inv = 1.f/s;
    p[lane] = ea*inv; p[lane+32] = eb*inv;
}

// ---------------- integrate reads -------------------------------------------
__global__ void integrate_k(const float* __restrict__ Hf, const float* __restrict__ pms,
                            const float* __restrict__ q, const float* __restrict__ cem,
                            float* __restrict__ out)
{
    const int r = blockIdx.x, s = r >> 10, n = r & (SEQ-1);
    long long base = (long long)r*DM + threadIdx.x*4;
    float4 hv = *reinterpret_cast<const float4*>(Hf + base);
    float4 pv = *reinterpret_cast<const float4*>(pms + base);
    float4 cv = *reinterpret_cast<const float4*>(cem + base);
    float4 a;
    a.x = hv.x*pv.x + cv.x; a.y = hv.y*pv.y + cv.y;
    a.z = hv.z*pv.z + cv.z; a.w = hv.w*pv.w + cv.w;
    #pragma unroll
    for (int b=0;b<NBK;b++){
        float4 qv = *reinterpret_cast<const float4*>(
            q + (((long long)(s*NBK+b))*SEQ + n)*DM + threadIdx.x*4);
        a.x += qv.x; a.y += qv.y; a.z += qv.z; a.w += qv.w;
    }
    *reinterpret_cast<float4*>(out + base) = a;
}

// ---------------- final LN --------------------------------------------------
__global__ void finalln_k(const float* __restrict__ X, const float* __restrict__ g,
                          const float* __restrict__ b, float* __restrict__ O)
{
    __shared__ float sred[32];
    const int r = blockIdx.x, tid = threadIdx.x;
    long long base = (long long)r*DM + tid*4;
    float4 v = *reinterpret_cast<const float4*>(X + base);
    float s1 = v.x+v.y+v.z+v.w;
    float mu = blockSum256(s1, sred)*(1.f/(float)DM);
    float dx=v.x-mu, dy=v.y-mu, dz=v.z-mu, dw=v.w-mu;
    float s2 = dx*dx+dy*dy+dz*dz+dw*dw;
    float inv = rsqrtf(blockSum256(s2, sred)*(1.f/(float)DM) + 1e-5f);
    float4 gv = *reinterpret_cast<const float4*>(g + tid*4);
    float4 bv = *reinterpret_cast<const float4*>(b + tid*4);
    float4 o;
    o.x = dx*inv*gv.x+bv.x; o.y = dy*inv*gv.y+bv.y;
    o.z = dz*inv*gv.z+bv.z; o.w = dw*inv*gv.w+bv.w;
    *reinterpret_cast<float4*>(O + base) = o;
}

__global__ void auxfin_k(const float* __restrict__ auxp, float* __restrict__ out)
{
    __shared__ float sred[32];
    float a = 0.f;
    for (int i = threadIdx.x; i < 2048; i += 256) a += auxp[i];
    float t = blockSum256(a, sred);
    if (threadIdx.x==0) out[LOGN] = t * (0.1f/((float)NR*(float)DM));
}

// ---------------- host ------------------------------------------------------
extern "C" void kernel_launch(void* const* d_in, const int* in_sizes, int n_in,
                              void* d_out, int out_size)
{
    const int*   ids   = (const int*)  d_in[0];
    const float* emb   = (const float*)d_in[1];
    const float* pos   = (const float*)d_in[2];
    const float* s1Win = (const float*)d_in[3];
    const float* s1Wg  = (const float*)d_in[4];
    const float* s1Wo  = (const float*)d_in[5];
    const float* s1g   = (const float*)d_in[6];
    const float* s1b   = (const float*)d_in[7];
    const float* s3Win = (const float*)d_in[8];
    const float* s3Wg  = (const float*)d_in[9];
    const float* s3Wo  = (const float*)d_in[10];
    const float* s3g   = (const float*)d_in[11];
    const float* s3b   = (const float*)d_in[12];
    const float* Wseed = (const float*)d_in[13];
    const float* Ww    = (const float*)d_in[14];
    const float* Wpred = (const float*)d_in[15];
    const float* Wnv   = (const float*)d_in[16];
    const float* Wnb   = (const float*)d_in[17];
    const float* Wdel  = (const float*)d_in[18];
    const float* pmst  = (const float*)d_in[19];
    const float* emK   = (const float*)d_in[20];
    const float* emV   = (const float*)d_in[21];
    const float* lng   = (const float*)d_in[22];
    const float* lnb   = (const float*)d_in[23];
    float* out = (float*)d_out;

    float *X, *H, *bZ, *bA, *S, *seed, *wc, *pms, *lno, *dpm, *q, *sim;
    float *wnv, *smg, *nvs, *wiv, *kiv, *auxp;
    cudaGetSymbolAddress((void**)&X, g_X);
    cudaGetSymbolAddress((void**)&H, g_H);
    cudaGetSymbolAddress((void**)&bZ, g_bufZ);
    cudaGetSymbolAddress((void**)&bA, g_bufA);
    cudaGetSymbolAddress((void**)&S, g_surp);
    cudaGetSymbolAddress((void**)&seed, g_seed);
    cudaGetSymbolAddress((void**)&wc, g_wc);
    cudaGetSymbolAddress((void**)&pms, g_pms);
    cudaGetSymbolAddress((void**)&lno, g_lno);
    cudaGetSymbolAddress((void**)&dpm, g_dpm);
    cudaGetSymbolAddress((void**)&q, g_q);
    cudaGetSymbolAddress((void**)&sim, g_sim);
    cudaGetSymbolAddress((void**)&wnv, g_wnv);
    cudaGetSymbolAddress((void**)&smg, g_smg);
    cudaGetSymbolAddress((void**)&nvs, g_nvs);
    cudaGetSymbolAddress((void**)&wiv, g_wiv);
    cudaGetSymbolAddress((void**)&kiv, g_kiv);
    cudaGetSymbolAddress((void**)&auxp, g_aux);

    const long long sND = (long long)SEQ*DM;         // 1048576
    const long long sMD = (long long)MS*DM;          // 65536
    const long long sNM = (long long)SEQ*MS;         // 65536

    embed_k<<<NR,256>>>(ids, emb, pos, X, H);

    for (int l=0;l<2;l++){
        lnproj_k<<<dim3(CC,NR/32),256>>>(H, s1Win+l*CC*DC*EE, s1Wg+l*CC*DC*EE,
                                         s1g+l*DC, s1b+l*DC, bZ, bA);
        scan_k<<<32,256>>>(bZ, bA);
        outproj_k<<<dim3(CC,NR/16),256>>>(bZ, s1Wo+l*CC*EE*DC, H);
    }

    pcm_k<<<dim3(CC,NR/32),256>>>(H, X, Wpred, S, auxp);
    seedw_k<<<dim3(CC,NR/32),256>>>(H, Wseed, Ww, seed, wc);
    rowstat_k<<<NR,256>>>(S, wc, H, Wnv, Wnb, smg, wiv, wnv);
    knorm_k<<<BSZ*NBK*MS,256>>>(emK, kiv);

    // similarity: w_cand @ em_K^T per (s,b)   (uses raw surp? no — uses wc; ok before cumsum)
    sgemm_k<true><<<dim3(1,SEQ/128,BSZ*NBK),256>>>(wc, emK, sim,
        SEQ, MS, DM, DM, DM, MS, sND, sMD, sNM, NBK, 1.f);
    novel_k<<<NR,256>>>(sim, wnv, smg, wiv, kiv, nvs);
    cem_k<<<NR,256>>>(nvs, wc, bZ);          // reuse bufZ as cum_em accumulator
    cumsum_k<<<16,256>>>(bZ);

    // procedural memory: cumsum(surp) then 8 batched GEMMs vs W_delta
    cumsum_k<<<16,256>>>(S);
    sgemm_k<false><<<dim3(DM/128,NR/128,NBK),256>>>(S, Wdel, dpm,
        NR, DM, DM, DM, DM, DM, 0, (long long)DM*DM, (long long)NR*DM, NBK, 1.f);
    pmsum_k<<<NR,256>>>(dpm, pmst, pms);

    // trail attention
    qinit_k<<<8192,256>>>(seed, q);
    for (int t=0;t<4;t++){
        sgemm_k<true><<<dim3(1,SEQ/128,BSZ*NBK),256>>>(q, emK, sim,
            SEQ, MS, DM, DM, DM, MS, sND, sMD, sNM, 1, 1.f);
        softmax_k<<<BSZ*NBK*SEQ/8,256>>>(sim);
        sgemm_k<false><<<dim3(DM/128,SEQ/128,BSZ*NBK),256>>>(sim, emV, q,
            SEQ, DM, MS, MS, DM, DM, sNM, sMD, sND, 1, 1.f);
    }

    integrate_k<<<NR,256>>>(H, pms, q, bZ, X);

    for (int l=0;l<2;l++){
        lnproj_k<<<dim3(CC,NR/32),256>>>(X, s3Win+l*CC*DC*EE, s3Wg+l*CC*DC*EE,
                                         s3g+l*DC, s3b+l*DC, bZ, bA);
        scan_k<<<32,256>>>(bZ, bA);
        outproj_k<<<dim3(CC,NR/16),256>>>(bZ, s3Wo+l*CC*EE*DC, X);
    }

    finalln_k<<<NR,256>>>(X, lng, lnb, lno);

    // logits: lno [4096,1024] @ emb^T [1024,32000]
    sgemm_k<true><<<dim3(VOC/128,NR/128,1),256>>>(lno, emb, out,
        NR, VOC, DM, DM, DM, VOC, 0, 0, 0, 1, 1.f);

    if ((long long)out_size > LOGN)
        auxfin_k<<<1,256>>>(auxp, out);
}

// round 7
// speedup vs baseline: 1.2469x; 1.2469x over previous
#include <cuda_runtime.h>
#include <cuda_bf16.h>
#include <math.h>

#define BSZ 4
#define SEQ 1024
#define VOC 32000
#define DM 1024
#define CC 16
#define DC 64
#define NBK 8
#define MS 64
#define EE 128
#define NR (BSZ*SEQ)
#define LOGN ((long long)NR*VOC)

// ---------------- scratch ----------------------------------------------------
__device__ float g_X[NR*DM];
__device__ float g_H[NR*DM];
__device__ float g_bufZ[NR*CC*EE];
__device__ float g_bufA[NR*CC*EE];
__device__ float g_surp[NR*DM];
__device__ float g_seed[NR*DM];
__device__ float g_wc[NR*DM];
__device__ float g_pms[NR*DM];
__device__ float g_lno[NR*DM];
__device__ float g_dpm[(long long)NBK*NR*DM];
__device__ float g_q[(long long)BSZ*NBK*SEQ*DM];
__device__ float g_sim[(long long)BSZ*NBK*SEQ*MS];
__device__ float g_wnv[NR*NBK];
__device__ float g_smg[NR];
__device__ float g_nvs[NR];
__device__ float g_wiv[NR];
__device__ float g_kiv[BSZ*NBK*MS];
__device__ float g_aux[2048];

__device__ __forceinline__ float sigm(float x){ return 1.f/(1.f+expf(-x)); }

__device__ __forceinline__ float blockSum256(float v, float* sred){
    __syncthreads();
    int lane = threadIdx.x & 31, w = threadIdx.x >> 5;
    #pragma unroll
    for (int o=16;o;o>>=1) v += __shfl_xor_sync(0xffffffffu, v, o);
    if (lane==0) sred[w]=v;
    __syncthreads();
    float t = (threadIdx.x<8)? sred[threadIdx.x] : 0.f;
    if (w==0){
        #pragma unroll
        for (int o=4;o;o>>=1) t += __shfl_xor_sync(0xffffffffu, t, o);
        if (lane==0) sred[0]=t;
    }
    __syncthreads();
    return sred[0];
}

// ---------------- tensor-core GEMM: bf16 2-term split, fp32-accurate ---------
// C[z] = alpha * A[z/zdivA] * op(B[z]).  TB: B row-major [Ncols,K] (uses B^T).
// M%128==0, K%16==0. Ncols guarded (loads + stores).
__device__ __forceinline__ unsigned packhl(float x){
    __nv_bfloat16 h = __float2bfloat16(x);
    float hf = __bfloat162float(h);
    __nv_bfloat16 l = __float2bfloat16(x - hf);
    return (unsigned)__bfloat16_as_ushort(h) | ((unsigned)__bfloat16_as_ushort(l) << 16);
}
__device__ __forceinline__ void mma16816(float* c, const unsigned* a, unsigned b0, unsigned b1){
    asm volatile("mma.sync.aligned.m16n8k16.row.col.f32.bf16.bf16.f32 "
        "{%0,%1,%2,%3}, {%4,%5,%6,%7}, {%8,%9}, {%0,%1,%2,%3};"
        : "+f"(c[0]), "+f"(c[1]), "+f"(c[2]), "+f"(c[3])
        : "r"(a[0]), "r"(a[1]), "r"(a[2]), "r"(a[3]), "r"(b0), "r"(b1));
}

template<bool TB>
__global__ void __launch_bounds__(256)
hgemm_k(const float* __restrict__ Ag, const float* __restrict__ Bg, float* __restrict__ Cg,
        int M, int Ncols, int K, int lda, int ldb, int ldc,
        long long sA, long long sB, long long sC, int zdivA, float alpha)
{
    __shared__ unsigned As[2][16][136];
    __shared__ unsigned Bs[2][16][136];
    const int z = blockIdx.z;
    const float* A = Ag + (long long)(z/zdivA)*sA;
    const float* B = Bg + (long long)z*sB;
    float* C = Cg + (long long)z*sC;
    const int m0 = blockIdx.y*128, n0 = blockIdx.x*128;
    const int tid = threadIdx.x;
    const int wid = tid>>5, lane = tid&31;
    const int wm = (wid&1)*64, wn = (wid>>1)*32;
    const int r = lane>>2, cp = lane&3;
    // staging maps
    const int arow = tid>>1, akq = (tid&1)*8;          // A (and TB-B): 128 rows x 16 k
    const int bk = tid>>4, bn = (tid&15)*8;            // NN-B: 16 k x 128 n

    float acc[16][4];
    #pragma unroll
    for (int i=0;i<16;i++){ acc[i][0]=0.f; acc[i][1]=0.f; acc[i][2]=0.f; acc[i][3]=0.f; }

    const int nk = K >> 4;

    auto ldA = [&](int kb, float4* v){
        const float* p = A + (long long)(m0+arow)*lda + kb + akq;
        v[0] = *reinterpret_cast<const float4*>(p);
        v[1] = *reinterpret_cast<const float4*>(p+4);
    };
    auto stA = [&](const float4* v, int s){
        const float* f = reinterpret_cast<const float*>(v);
        #pragma unroll
        for (int j=0;j<8;j++) As[s][akq+j][arow] = packhl(f[j]);
    };
    auto ldB = [&](int kb, float4* v){
        if (TB){
            int nc = n0 + arow;                        // FIX: include n0
            if (nc < Ncols){
                const float* p = B + (long long)nc*ldb + kb + akq;
                v[0] = *reinterpret_cast<const float4*>(p);
                v[1] = *reinterpret_cast<const float4*>(p+4);
            } else {
                v[0] = make_float4(0,0,0,0); v[1] = make_float4(0,0,0,0);
            }
        } else {
            const float* p = B + (long long)(kb+bk)*ldb + n0 + bn;
            v[0] = *reinterpret_cast<const float4*>(p);
            v[1] = *reinterpret_cast<const float4*>(p+4);
        }
    };
    auto stB = [&](const float4* v, int s){
        const float* f = reinterpret_cast<const float*>(v);
        if (TB){
            #pragma unroll
            for (int j=0;j<8;j++) Bs[s][akq+j][arow] = packhl(f[j]);
        } else {
            #pragma unroll
            for (int j=0;j<8;j++) Bs[s][bk][bn+j] = packhl(f[j]);
        }
    };

    float4 va[2], vb[2];
    ldA(0, va); ldB(0, vb);
    stA(va, 0); stB(vb, 0);
    __syncthreads();
    for (int t=0; t<nk; t++){
        const int s = t & 1;
        const bool has = (t+1 < nk);
        if (has){ ldA((t+1)<<4, va); ldB((t+1)<<4, vb); }
        #pragma unroll
        for (int vk=0; vk<2; vk++){
            const int k8 = vk*8;
            unsigned a[4][4];
            #pragma unroll
            for (int i=0;i<4;i++){
                int mb = wm + i*16;
                a[i][0] = As[s][k8+cp][mb+r];
                a[i][1] = As[s][k8+cp][mb+r+8];
                a[i][2] = As[s][k8+cp+4][mb+r];
                a[i][3] = As[s][k8+cp+4][mb+r+8];
            }
            unsigned w0[4], w1[4];
            #pragma unroll
            for (int j=0;j<4;j++){
                w0[j] = Bs[s][k8+cp][wn+j*8+r];
                w1[j] = Bs[s][k8+cp+4][wn+j*8+r];
            }
            #pragma unroll
            for (int i=0;i<4;i++)
                #pragma unroll
                for (int j=0;j<4;j++){
                    mma16816(acc[i*4+j], a[i],
                             __byte_perm(w0[j], 0, 0x1010), __byte_perm(w1[j], 0, 0x1010));
                    mma16816(acc[i*4+j], a[i], w0[j]>>16, w1[j]>>16);
                }
        }
        __syncthreads();
        if (has){ stA(va, s^1); stB(vb, s^1); __syncthreads(); }
    }
    #pragma unroll
    for (int i=0;i<4;i++){
        #pragma unroll
        for (int j=0;j<4;j++){
            const float* c = acc[i*4+j];
            int row = m0 + wm + i*16 + r;
            int col = n0 + wn + j*8 + 2*cp;
            if (col < Ncols){
                float2 v0 = make_float2(alpha*c[0], alpha*c[1]);
                float2 v1 = make_float2(alpha*c[2], alpha*c[3]);
                *reinterpret_cast<float2*>(C + (long long)row*ldc + col) = v0;
                *reinterpret_cast<float2*>(C + (long long)(row+8)*ldc + col) = v1;
            }
        }
    }
}

// ---------------- embedding -------------------------------------------------
__global__ void embed_k(const int* __restrict__ ids, const float* __restrict__ emb,
                        const float* __restrict__ pos, float* __restrict__ X, float* __restrict__ H)
{
    int r = blockIdx.x, n = r & (SEQ-1);
    const float* ep = emb + (long long)ids[r]*DM;
    const float* pp = pos + (long long)n*DM;
    for (int d = threadIdx.x; d < DM; d += 256){
        float v = ep[d] + pp[d];
        X[(long long)r*DM+d] = v; H[(long long)r*DM+d] = v;
    }
}

// ---------------- scan layer: LN + z/a projections --------------------------
__global__ void __launch_bounds__(256)
lnproj_k(const float* __restrict__ H, const float* __restrict__ Win, const float* __restrict__ Wg,
         const float* __restrict__ gam, const float* __restrict__ bet,
         float* __restrict__ bufZ, float* __restrict__ bufA)
{
    __shared__ float sX[32][64];
    __shared__ float sW[64*128];
    const int c = blockIdx.x, r0 = blockIdx.y*32, tid = threadIdx.x;
    for (int i=tid;i<32*64;i+=256){
        int row=i>>6, d=i&63;
        sX[row][d] = H[(((long long)(r0+row))*CC+c)*DC+d];
    }
    __syncthreads();
    const int w = tid>>5, lane = tid&31;
    for (int row=w; row<32; row+=8){
        float x0=sX[row][lane], x1=sX[row][lane+32];
        float sm=x0+x1;
        #pragma unroll
        for (int o=16;o;o>>=1) sm += __shfl_xor_sync(0xffffffffu, sm, o);
        float mu = sm*(1.f/64.f);
        float d0=x0-mu, d1=x1-mu;
        float vs=d0*d0+d1*d1;
        #pragma unroll
        for (int o=16;o;o>>=1) vs += __shfl_xor_sync(0xffffffffu, vs, o);
        float inv = rsqrtf(vs*(1.f/64.f)+1e-5f);
        sX[row][lane]    = d0*inv*gam[lane]   +bet[lane];
        sX[row][lane+32] = d1*inv*gam[lane+32]+bet[lane+32];
    }
    __syncthreads();
    for (int i=tid;i<64*128/4;i+=256)
        reinterpret_cast<float4*>(sW)[i] = reinterpret_cast<const float4*>(Win + c*64*128)[i];
    __syncthreads();
    for (int qd=tid; qd<1024; qd+=256){
        int row=qd>>5, e0=(qd&31)<<2;
        float4 a=make_float4(0,0,0,0);
        #pragma unroll 8
        for (int d=0;d<64;d++){
            float xv=sX[row][d];
            float4 wv=*reinterpret_cast<const float4*>(&sW[d*128+e0]);
            a.x=fmaf(xv,wv.x,a.x); a.y=fmaf(xv,wv.y,a.y); a.z=fmaf(xv,wv.z,a.z); a.w=fmaf(xv,wv.w,a.w);
        }
        *reinterpret_cast<float4*>(&bufZ[(((long long)(r0+row))*CC+c)*EE+e0]) = a;
    }
    __syncthreads();
    for (int i=tid;i<64*128/4;i+=256)
        reinterpret_cast<float4*>(sW)[i] = reinterpret_cast<const float4*>(Wg + c*64*128)[i];
    __syncthreads();
    for (int qd=tid; qd<1024; qd+=256){
        int row=qd>>5, e0=(qd&31)<<2;
        float4 a=make_float4(0,0,0,0);
        #pragma unroll 8
        for (int d=0;d<64;d++){
            float xv=sX[row][d];
            float4 wv=*reinterpret_cast<const float4*>(&sW[d*128+e0]);
            a.x=fmaf(xv,wv.x,a.x); a.y=fmaf(xv,wv.y,a.y); a.z=fmaf(xv,wv.z,a.z); a.w=fmaf(xv,wv.w,a.w);
        }
        a.x=sigm(a.x); a.y=sigm(a.y); a.z=sigm(a.z); a.w=sigm(a.w);
        *reinterpret_cast<float4*>(&bufA[(((long long)(r0+row))*CC+c)*EE+e0]) = a;
    }
}

// ---------------- gated recurrence over time --------------------------------
__global__ void scan_k(float* __restrict__ Z, const float* __restrict__ A)
{
    int ch = blockIdx.x*256 + threadIdx.x;
    const int str = CC*EE;
    long long p = (long long)(ch>>11)*((long long)SEQ*str) + (ch & (str-1));
    float h = 0.f;
    for (int n=0;n<SEQ;n+=4){
        float z0=Z[p], z1=Z[p+str], z2=Z[p+2*str], z3=Z[p+3*str];
        float a0=A[p], a1=A[p+str], a2=A[p+2*str], a3=A[p+3*str];
        h = fmaf(a0, h-z0, z0); Z[p]=h;
        h = fmaf(a1, h-z1, z1); Z[p+str]=h;
        h = fmaf(a2, h-z2, z2); Z[p+2*str]=h;
        h = fmaf(a3, h-z3, z3); Z[p+3*str]=h;
        p += 4*str;
    }
}

// ---------------- scan output projection + residual -------------------------
__global__ void __launch_bounds__(256)
outproj_k(const float* __restrict__ hbuf, const float* __restrict__ Wout, float* __restrict__ H)
{
    __shared__ float sh[16][128];
    __shared__ float sW[128*64];
    const int c = blockIdx.x, r0 = blockIdx.y*16, tid = threadIdx.x;
    for (int i=tid;i<16*128/4;i+=256){
        int row=i>>5, e0=(i&31)<<2;
        *reinterpret_cast<float4*>(&sh[row][e0]) =
            *reinterpret_cast<const float4*>(&hbuf[(((long long)(r0+row))*CC+c)*EE+e0]);
    }
    for (int i=tid;i<128*64/4;i+=256)
        reinterpret_cast<float4*>(sW)[i] = reinterpret_cast<const float4*>(Wout + c*128*64)[i];
    __syncthreads();
    int row = tid>>4, d0 = (tid&15)<<2;
    float4 a=make_float4(0,0,0,0);
    #pragma unroll 8
    for (int e=0;e<128;e++){
        float hv=sh[row][e];
        float4 wv=*reinterpret_cast<const float4*>(&sW[e*64+d0]);
        a.x=fmaf(hv,wv.x,a.x); a.y=fmaf(hv,wv.y,a.y); a.z=fmaf(hv,wv.z,a.z); a.w=fmaf(hv,wv.w,a.w);
    }
    long long o = (((long long)(r0+row))*CC+c)*DC+d0;
    float4 h0 = *reinterpret_cast<const float4*>(&H[o]);
    a.x+=h0.x; a.y+=h0.y; a.z+=h0.z; a.w+=h0.w;
    *reinterpret_cast<float4*>(&H[o]) = a;
}

// ---------------- PCM -------------------------------------------------------
__global__ void __launch_bounds__(256)
pcm_k(float* __restrict__ H, const float* __restrict__ X, const float* __restrict__ Wpred,
      float* __restrict__ surp, float* __restrict__ auxp)
{
    __shared__ float sH[32][64];
    __shared__ float sW[64*64];
    __shared__ float sred[32];
    const int c = blockIdx.x, r0 = blockIdx.y*32, tid = threadIdx.x;
    for (int i=tid;i<32*64;i+=256){
        int row=i>>6, d=i&63;
        sH[row][d] = H[(((long long)(r0+row))*CC+c)*DC+d];
    }
    for (int i=tid;i<64*64/4;i+=256)
        reinterpret_cast<float4*>(sW)[i] = reinterpret_cast<const float4*>(Wpred + c*64*64)[i];
    __syncthreads();
    float auxa = 0.f;
    for (int qd=tid; qd<512; qd+=256){
        int row=qd>>4, d0=(qd&15)<<2;
        float4 a=make_float4(0,0,0,0);
        #pragma unroll 8
        for (int d=0;d<64;d++){
            float hv=sH[row][d];
            float4 wv=*reinterpret_cast<const float4*>(&sW[d*64+d0]);
            a.x=fmaf(hv,wv.x,a.x); a.y=fmaf(hv,wv.y,a.y); a.z=fmaf(hv,wv.z,a.z); a.w=fmaf(hv,wv.w,a.w);
        }
        long long gi = (((long long)(r0+row))*CC+c)*DC+d0;
        float4 xv = *reinterpret_cast<const float4*>(&X[gi]);
        float dx=a.x-xv.x, dy=a.y-xv.y, dz=a.z-xv.z, dw=a.w-xv.w;
        auxa += dx*dx+dy*dy+dz*dz+dw*dw;
        float4 sp = make_float4(fabsf(dx),fabsf(dy),fabsf(dz),fabsf(dw));
        *reinterpret_cast<float4*>(&surp[gi]) = sp;
        float4 hn;
        hn.x = sH[row][d0+0]*(1.f+tanhf(sp.x));
        hn.y = sH[row][d0+1]*(1.f+tanhf(sp.y));
        hn.z = sH[row][d0+2]*(1.f+tanhf(sp.z));
        hn.w = sH[row][d0+3]*(1.f+tanhf(sp.w));
        *reinterpret_cast<float4*>(&H[gi]) = hn;
    }
    float tot = blockSum256(auxa, sred);
    if (tid==0) auxp[blockIdx.y*CC + c] = tot;
}

// ---------------- seed & w_cand ---------------------------------------------
__global__ void __launch_bounds__(256)
seedw_k(const float* __restrict__ H, const float* __restrict__ Ws, const float* __restrict__ Ww,
        float* __restrict__ seed, float* __restrict__ wc)
{
    __shared__ float sH[32][64];
    __shared__ float sWa[64*64];
    __shared__ float sWb[64*64];
    const int c = blockIdx.x, r0 = blockIdx.y*32, tid = threadIdx.x;
    for (int i=tid;i<32*64;i+=256){
        int row=i>>6, d=i&63;
        sH[row][d] = H[(((long long)(r0+row))*CC+c)*DC+d];
    }
    for (int i=tid;i<64*64/4;i+=256){
        reinterpret_cast<float4*>(sWa)[i] = reinterpret_cast<const float4*>(Ws + c*64*64)[i];
        reinterpret_cast<float4*>(sWb)[i] = reinterpret_cast<const float4*>(Ww + c*64*64)[i];
    }
    __syncthreads();
    for (int qd=tid; qd<512; qd+=256){
        int row=qd>>4, d0=(qd&15)<<2;
        float4 a=make_float4(0,0,0,0), b=make_float4(0,0,0,0);
        #pragma unroll 8
        for (int d=0;d<64;d++){
            float hv=sH[row][d];
            float4 wa=*reinterpret_cast<const float4*>(&sWa[d*64+d0]);
            float4 wb=*reinterpret_cast<const float4*>(&sWb[d*64+d0]);
            a.x=fmaf(hv,wa.x,a.x); a.y=fmaf(hv,wa.y,a.y); a.z=fmaf(hv,wa.z,a.z); a.w=fmaf(hv,wa.w,a.w);
            b.x=fmaf(hv,wb.x,b.x); b.y=fmaf(hv,wb.y,b.y); b.z=fmaf(hv,wb.z,b.z); b.w=fmaf(hv,wb.w,b.w);
        }
        long long gi = (((long long)(r0+row))*CC+c)*DC+d0;
        *reinterpret_cast<float4*>(&seed[gi]) = a;
        *reinterpret_cast<float4*>(&wc[gi]) = b;
    }
}

// ---------------- per-row stats ---------------------------------------------
__global__ void __launch_bounds__(256)
rowstat_k(const float* __restrict__ surp, const float* __restrict__ wc,
          const float* __restrict__ Hf, const float* __restrict__ Wnv,
          const float* __restrict__ Wnb, float* __restrict__ smg,
          float* __restrict__ wiv, float* __restrict__ wnv)
{
    __shared__ float sred[32];
    const int r = blockIdx.x, tid = threadIdx.x;
    long long base = (long long)r*DM + tid*4;
    float4 sv = *reinterpret_cast<const float4*>(surp + base);
    float4 wv = *reinterpret_cast<const float4*>(wc + base);
    float4 hv = *reinterpret_cast<const float4*>(Hf + base);
    float s1 = sv.x+sv.y+sv.z+sv.w;
    float s2 = wv.x*wv.x+wv.y*wv.y+wv.z*wv.z+wv.w*wv.w;
    float t1 = blockSum256(s1, sred);
    if (tid==0) smg[r] = sigm(t1*(1.f/(float)DM));
    float t2 = blockSum256(s2, sred);
    if (tid==0) wiv[r] = 1.f/(sqrtf(t2)+1e-6f);
    float acc[NBK];
    #pragma unroll
    for (int b=0;b<NBK;b++) acc[b]=0.f;
    float hvv[4] = {hv.x,hv.y,hv.z,hv.w};
    #pragma unroll
    for (int j=0;j<4;j++){
        const float* wr = Wnv + (tid*4+j)*NBK;
        #pragma unroll
        for (int b=0;b<NBK;b++) acc[b] = fmaf(hvv[j], wr[b], acc[b]);
    }
    #pragma unroll
    for (int b=0;b<NBK;b++){
        float t = blockSum256(acc[b], sred);
        if (tid==0) wnv[r*NBK+b] = sigm(t + Wnb[b]);
    }
}

// ---------------- em_K inverse norms ----------------------------------------
__global__ void knorm_k(const float* __restrict__ emK, float* __restrict__ kiv)
{
    __shared__ float sred[32];
    const int row = blockIdx.x;
    float4 v = *reinterpret_cast<const float4*>(emK + (long long)row*DM + threadIdx.x*4);
    float s = v.x*v.x+v.y*v.y+v.z*v.z+v.w*v.w;
    float t = blockSum256(s, sred);
    if (threadIdx.x==0) kiv[row] = 1.f/(sqrtf(t)+1e-6f);
}

// ---------------- in-place causal cumsum over time --------------------------
__global__ void cumsum_k(float* __restrict__ X)
{
    int ch = blockIdx.x*256 + threadIdx.x;
    long long p = (long long)(ch>>10)*((long long)SEQ*DM) + (ch & (DM-1));
    float h = 0.f;
    for (int n=0;n<SEQ;n+=4){
        float v0=X[p], v1=X[p+DM], v2=X[p+2*DM], v3=X[p+3*DM];
        h+=v0; X[p]=h; h+=v1; X[p+DM]=h; h+=v2; X[p+2*DM]=h; h+=v3; X[p+3*DM]=h;
        p += 4*DM;
    }
}

// ---------------- pm sigmoid-sum epilogue -----------------------------------
__global__ void pmsum_k(const float* __restrict__ dpm, const float* __restrict__ pmst,
                        float* __restrict__ pms)
{
    const int r = blockIdx.x, s = r >> 10;
    for (int d = threadIdx.x; d < DM; d += 256){
        float acc = 0.f;
        #pragma unroll
        for (int b=0;b<NBK;b++)
            acc += sigm(pmst[((long long)s*NBK+b)*DM+d] + dpm[((long long)b*NR + r)*DM + d]);
        pms[(long long)r*DM+d] = acc;
    }
}

// ---------------- novelty -> summed write gate ------------------------------
__global__ void novel_k(const float* __restrict__ sim, const float* __restrict__ wnv,
                        const float* __restrict__ smg, const float* __restrict__ wiv,
                        const float* __restrict__ kiv, float* __restrict__ nvs)
{
    __shared__ float snov[NBK];
    const int r = blockIdx.x, s = r >> 10, n = r & (SEQ-1);
    const int b = threadIdx.x >> 5, lane = threadIdx.x & 31;
    const int z = s*NBK + b;
    const float* sp = sim + ((long long)z*SEQ + n)*MS;
    const float* kp = kiv + z*MS;
    float m = fmaxf(sp[lane]*kp[lane], sp[lane+32]*kp[lane+32]);
    #pragma unroll
    for (int o=16;o;o>>=1) m = fmaxf(m, __shfl_xor_sync(0xffffffffu, m, o));
    if (lane==0){
        float msim = m * wiv[r];
        snov[b] = wnv[r*NBK+b] * smg[r] * fmaxf(0.f, 1.f - msim);
    }
    __syncthreads();
    if (threadIdx.x==0){
        float t=0.f;
        #pragma unroll
        for (int i=0;i<NBK;i++) t += snov[i];
        nvs[r] = t;
    }
}

__global__ void cem_k(const float* __restrict__ nvs, const float* __restrict__ wc,
                      float* __restrict__ cem)
{
    const int r = blockIdx.x;
    float nv = nvs[r];
    long long base = (long long)r*DM + threadIdx.x*4;
    float4 v = *reinterpret_cast<const float4*>(wc + base);
    v.x*=nv; v.y*=nv; v.z*=nv; v.w*=nv;
    *reinterpret_cast<float4*>(cem + base) = v;
}

// ---------------- trail attention pieces ------------------------------------
__global__ void qinit_k(const float* __restrict__ seed, float* __restrict__ q)
{
    long long f = (long long)blockIdx.x*256 + threadIdx.x;
    const long long per = (long long)SEQ*DM/4;
    for (int it=0; it<4; it++, f += (long long)8192*256){
        long long z = f / per, rem = f - z*per;
        long long s = z >> 3;
        reinterpret_cast<float4*>(q)[f] =
            reinterpret_cast<const float4*>(seed)[s*per + rem];
    }
}

__global__ void softmax_k(float* __restrict__ sim)
{
    const int row = blockIdx.x*8 + (threadIdx.x>>5);
    const int lane = threadIdx.x & 31;
    float* p = sim + (long long)row*MS;
    const float scale = 0.03125f;
    float a = p[lane]*scale, b = p[lane+32]*scale;
    float m = fmaxf(a,b);
    #pragma unroll
    for (int o=16;o;o>>=1) m = fmaxf(m, __shfl_xor_sync(0xffffffffu, m, o));
    float ea = expf(a-m), eb = expf(b-m);
    float s = ea+eb;
    #pragma unroll
    for (int o=16;o;o>>=1) s += __shfl_xor_sync(0xffffffffu, s, o);
    float inv = 1.f/s;
    p[lane] = ea*inv; p[lane+32] = eb*inv;
}

// ---------------- integrate reads -------------------------------------------
__global__ void integrate_k(const float* __restrict__ Hf, const float* __restrict__ pms,
                            const float* __restrict__ q, const float* __restrict__ cem,
                            float* __restrict__ out)
{
    const int r = blockIdx.x, s = r >> 10, n = r & (SEQ-1);
    long long base = (long long)r*DM + threadIdx.x*4;
    float4 hv = *reinterpret_cast<const float4*>(Hf + base);
    float4 pv = *reinterpret_cast<const float4*>(pms + base);
    float4 cv = *reinterpret_cast<const float4*>(cem + base);
    float4 a;
    a.x = hv.x*pv.x + cv.x; a.y = hv.y*pv.y + cv.y;
    a.z = hv.z*pv.z + cv.z; a.w = hv.w*pv.w + cv.w;
    #pragma unroll
    for (int b=0;b<NBK;b++){
        float4 qv = *reinterpret_cast<const float4*>(
            q + (((long long)(s*NBK+b))*SEQ + n)*DM + threadIdx.x*4);
        a.x += qv.x; a.y += qv.y; a.z += qv.z; a.w += qv.w;
    }
    *reinterpret_cast<float4*>(out + base) = a;
}

// ---------------- final LN --------------------------------------------------
__global__ void finalln_k(const float* __restrict__ X, const float* __restrict__ g,
                          const float* __restrict__ b, float* __restrict__ O)
{
    __shared__ float sred[32];
    const int r = blockIdx.x, tid = threadIdx.x;
    long long base = (long long)r*DM + tid*4;
    float4 v = *reinterpret_cast<const float4*>(X + base);
    float s1 = v.x+v.y+v.z+v.w;
    float mu = blockSum256(s1, sred)*(1.f/(float)DM);
    float dx=v.x-mu, dy=v.y-mu, dz=v.z-mu, dw=v.w-mu;
    float s2 = dx*dx+dy*dy+dz*dz+dw*dw;
    float inv = rsqrtf(blockSum256(s2, sred)*(1.f/(float)DM) + 1e-5f);
    float4 gv = *reinterpret_cast<const float4*>(g + tid*4);
    float4 bv = *reinterpret_cast<const float4*>(b + tid*4);
    float4 o;
    o.x = dx*inv*gv.x+bv.x; o.y = dy*inv*gv.y+bv.y;
    o.z = dz*inv*gv.z+bv.z; o.w = dw*inv*gv.w+bv.w;
    *reinterpret_cast<float4*>(O + base) = o;
}

__global__ void auxfin_k(const float* __restrict__ auxp, float* __restrict__ out)
{
    __shared__ float sred[32];
    float a = 0.f;
    for (int i = threadIdx.x; i < 2048; i += 256) a += auxp[i];
    float t = blockSum256(a, sred);
    if (threadIdx.x==0) out[LOGN] = t * (0.1f/((float)NR*(float)DM));
}

// ---------------- host ------------------------------------------------------
extern "C" void kernel_launch(void* const* d_in, const int* in_sizes, int n_in,
                              void* d_out, int out_size)
{
    const int*   ids   = (const int*)  d_in[0];
    const float* emb   = (const float*)d_in[1];
    const float* pos   = (const float*)d_in[2];
    const float* s1Win = (const float*)d_in[3];
    const float* s1Wg  = (const float*)d_in[4];
    const float* s1Wo  = (const float*)d_in[5];
    const float* s1g   = (const float*)d_in[6];
    const float* s1b   = (const float*)d_in[7];
    const float* s3Win = (const float*)d_in[8];
    const float* s3Wg  = (const float*)d_in[9];
    const float* s3Wo  = (const float*)d_in[10];
    const float* s3g   = (const float*)d_in[11];
    const float* s3b   = (const float*)d_in[12];
    const float* Wseed = (const float*)d_in[13];
    const float* Ww    = (const float*)d_in[14];
    const float* Wpred = (const float*)d_in[15];
    const float* Wnv   = (const float*)d_in[16];
    const float* Wnb   = (const float*)d_in[17];
    const float* Wdel  = (const float*)d_in[18];
    const float* pmst  = (const float*)d_in[19];
    const float* emK   = (const float*)d_in[20];
    const float* emV   = (const float*)d_in[21];
    const float* lng   = (const float*)d_in[22];
    const float* lnb   = (const float*)d_in[23];
    float* out = (float*)d_out;

    float *X, *H, *bZ, *bA, *S, *seed, *wc, *pms, *lno, *dpm, *q, *sim;
    float *wnv, *smg, *nvs, *wiv, *kiv, *auxp;
    cudaGetSymbolAddress((void**)&X, g_X);
    cudaGetSymbolAddress((void**)&H, g_H);
    cudaGetSymbolAddress((void**)&bZ, g_bufZ);
    cudaGetSymbolAddress((void**)&bA, g_bufA);
    cudaGetSymbolAddress((void**)&S, g_surp);
    cudaGetSymbolAddress((void**)&seed, g_seed);
    cudaGetSymbolAddress((void**)&wc, g_wc);
    cudaGetSymbolAddress((void**)&pms, g_pms);
    cudaGetSymbolAddress((void**)&lno, g_lno);
    cudaGetSymbolAddress((void**)&dpm, g_dpm);
    cudaGetSymbolAddress((void**)&q, g_q);
    cudaGetSymbolAddress((void**)&sim, g_sim);
    cudaGetSymbolAddress((void**)&wnv, g_wnv);
    cudaGetSymbolAddress((void**)&smg, g_smg);
    cudaGetSymbolAddress((void**)&nvs, g_nvs);
    cudaGetSymbolAddress((void**)&wiv, g_wiv);
    cudaGetSymbolAddress((void**)&kiv, g_kiv);
    cudaGetSymbolAddress((void**)&auxp, g_aux);

    const long long sND = (long long)SEQ*DM;
    const long long sMD = (long long)MS*DM;
    const long long sNM = (long long)SEQ*MS;

    embed_k<<<NR,256>>>(ids, emb, pos, X, H);

    for (int l=0;l<2;l++){
        lnproj_k<<<dim3(CC,NR/32),256>>>(H, s1Win+l*CC*DC*EE, s1Wg+l*CC*DC*EE,
                                         s1g+l*DC, s1b+l*DC, bZ, bA);
        scan_k<<<32,256>>>(bZ, bA);
        outproj_k<<<dim3(CC,NR/16),256>>>(bZ, s1Wo+l*CC*EE*DC, H);
    }

    pcm_k<<<dim3(CC,NR/32),256>>>(H, X, Wpred, S, auxp);
    seedw_k<<<dim3(CC,NR/32),256>>>(H, Wseed, Ww, seed, wc);
    rowstat_k<<<NR,256>>>(S, wc, H, Wnv, Wnb, smg, wiv, wnv);
    knorm_k<<<BSZ*NBK*MS,256>>>(emK, kiv);

    // similarity: w_cand @ em_K^T per (s,b)
    hgemm_k<true><<<dim3(1,SEQ/128,BSZ*NBK),256>>>(wc, emK, sim,
        SEQ, MS, DM, DM, DM, MS, sND, sMD, sNM, NBK, 1.f);
    novel_k<<<NR,256>>>(sim, wnv, smg, wiv, kiv, nvs);
    cem_k<<<NR,256>>>(nvs, wc, bZ);
    cumsum_k<<<16,256>>>(bZ);

    // procedural memory: cumsum(surp) then 8 batched GEMMs vs W_delta
    cumsum_k<<<16,256>>>(S);
    hgemm_k<false><<<dim3(DM/128,NR/128,NBK),256>>>(S, Wdel, dpm,
        NR, DM, DM, DM, DM, DM, 0, (long long)DM*DM, (long long)NR*DM, NBK, 1.f);
    pmsum_k<<<NR,256>>>(dpm, pmst, pms);

    // trail attention
    qinit_k<<<8192,256>>>(seed, q);
    for (int t=0;t<4;t++){
        hgemm_k<true><<<dim3(1,SEQ/128,BSZ*NBK),256>>>(q, emK, sim,
            SEQ, MS, DM, DM, DM, MS, sND, sMD, sNM, 1, 1.f);
        softmax_k<<<BSZ*NBK*SEQ/8,256>>>(sim);
        hgemm_k<false><<<dim3(DM/128,SEQ/128,BSZ*NBK),256>>>(sim, emV, q,
            SEQ, DM, MS, MS, DM, DM, sNM, sMD, sND, 1, 1.f);
    }

    integrate_k<<<NR,256>>>(H, pms, q, bZ, X);

    for (int l=0;l<2;l++){
        lnproj_k<<<dim3(CC,NR/32),256>>>(X, s3Win+l*CC*DC*EE, s3Wg+l*CC*DC*EE,
                                         s3g+l*DC, s3b+l*DC, bZ, bA);
        scan_k<<<32,256>>>(bZ, bA);
        outproj_k<<<dim3(CC,NR/16),256>>>(bZ, s3Wo+l*CC*EE*DC, X);
    }

    finalln_k<<<NR,256>>>(X, lng, lnb, lno);

    // logits: lno [4096,1024] @ emb^T [1024,32000]
    hgemm_k<true><<<dim3(VOC/128,NR/128,1),256>>>(lno, emb, out,
        NR, VOC, DM, DM, DM, VOC, 0, 0, 0, 1, 1.f);

    if ((long long)out_size > LOGN)
        auxfin_k<<<1,256>>>(auxp, out);
}

// round 9
// speedup vs baseline: 1.3187x; 1.0576x over previous
#include <cuda_runtime.h>
#include <cuda_bf16.h>
#include <math.h>

#define BSZ 4
#define SEQ 1024
#define VOC 32000
#define DM 1024
#define CC 16
#define DC 64
#define NBK 8
#define MS 64
#define EE 128
#define NR (BSZ*SEQ)
#define LOGN ((long long)NR*VOC)

// ---------------- float scratch ----------------------------------------------
__device__ float g_X[NR*DM];
__device__ float g_H[NR*DM];
__device__ float g_bufZ[NR*CC*EE];
__device__ float g_bufA[NR*CC*EE];
__device__ float g_surp[NR*DM];
__device__ float g_seed[NR*DM];
__device__ float g_wc[NR*DM];
__device__ float g_pms[NR*DM];
__device__ float g_dpm[(long long)NBK*NR*DM];
__device__ float g_q[(long long)BSZ*NBK*SEQ*DM];
__device__ float g_sim[(long long)BSZ*NBK*SEQ*MS];
__device__ float g_wnv[NR*NBK];
__device__ float g_smg[NR];
__device__ float g_nvs[NR];
__device__ float g_wiv[NR];
__device__ float g_kiv[BSZ*NBK*MS];
__device__ float g_aux[2048];

// ---------------- packed (hi-bf16 | lo-bf16) operand buffers ------------------
__device__ unsigned p_emb[(long long)VOC*DM];
__device__ unsigned p_wdel[(long long)NBK*DM*DM];
__device__ unsigned p_lno[NR*DM];
__device__ unsigned p_S[NR*DM];
__device__ unsigned p_wc[NR*DM];
__device__ unsigned p_emK[BSZ*NBK*MS*DM];
__device__ unsigned p_emV[BSZ*NBK*MS*DM];
__device__ unsigned p_q[(long long)BSZ*NBK*SEQ*DM];
__device__ unsigned p_sim[(long long)BSZ*NBK*SEQ*MS];

__device__ __forceinline__ float sigm(float x){ return 1.f/(1.f+expf(-x)); }

__device__ __forceinline__ unsigned packhl(float x){
    __nv_bfloat16 h = __float2bfloat16(x);
    float hf = __bfloat162float(h);
    __nv_bfloat16 l = __float2bfloat16(x - hf);
    return (unsigned)__bfloat16_as_ushort(h) | ((unsigned)__bfloat16_as_ushort(l) << 16);
}
__device__ __forceinline__ uint4 packhl4(float4 v){
    uint4 o; o.x=packhl(v.x); o.y=packhl(v.y); o.z=packhl(v.z); o.w=packhl(v.w); return o;
}

__device__ __forceinline__ float blockSum256(float v, float* sred){
    __syncthreads();
    int lane = threadIdx.x & 31, w = threadIdx.x >> 5;
    #pragma unroll
    for (int o=16;o;o>>=1) v += __shfl_xor_sync(0xffffffffu, v, o);
    if (lane==0) sred[w]=v;
    __syncthreads();
    float t = (threadIdx.x<8)? sred[threadIdx.x] : 0.f;
    if (w==0){
        #pragma unroll
        for (int o=4;o;o>>=1) t += __shfl_xor_sync(0xffffffffu, t, o);
        if (lane==0) sred[0]=t;
    }
    __syncthreads();
    return sred[0];
}

// ---------------- generic pack kernel ----------------------------------------
__global__ void pack_k(const float* __restrict__ in, unsigned* __restrict__ out, long long n4)
{
    long long i = (long long)blockIdx.x*256 + threadIdx.x;
    long long str = (long long)gridDim.x*256;
    for (; i < n4; i += str)
        reinterpret_cast<uint4*>(out)[i] = packhl4(reinterpret_cast<const float4*>(in)[i]);
}

// ---------------- tensor-core GEMM on pre-packed operands --------------------
// C[z] = alpha * A[z/zdivA] * op(B[z]).  TB: B row-major [Ncols,K] (uses B^T).
// A,B packed u32 (hi|lo bf16). M%128==0, K%16==0. Ncols guarded.
__device__ __forceinline__ void mma16816(float* c, const unsigned* a, unsigned b0, unsigned b1){
    asm volatile("mma.sync.aligned.m16n8k16.row.col.f32.bf16.bf16.f32 "
        "{%0,%1,%2,%3}, {%4,%5,%6,%7}, {%8,%9}, {%0,%1,%2,%3};"
        : "+f"(c[0]), "+f"(c[1]), "+f"(c[2]), "+f"(c[3])
        : "r"(a[0]), "r"(a[1]), "r"(a[2]), "r"(a[3]), "r"(b0), "r"(b1));
}

template<bool TB>
__global__ void __launch_bounds__(256)
hgemm_k(const unsigned* __restrict__ Ag, const unsigned* __restrict__ Bg,
        float* __restrict__ Cg, unsigned* __restrict__ Cpg,
        int M, int Ncols, int K, int lda, int ldb, int ldc,
        long long sA, long long sB, long long sC, int zdivA, float alpha)
{
    __shared__ unsigned As[2][16][136];
    __shared__ unsigned Bs[2][16][136];
    const int z = blockIdx.z;
    const unsigned* A = Ag + (long long)(z/zdivA)*sA;
    const unsigned* B = Bg + (long long)z*sB;
    float* C = Cg + (long long)z*sC;
    unsigned* Cp = Cpg ? (Cpg + (long long)z*sC) : (unsigned*)0;
    const int m0 = blockIdx.y*128, n0 = blockIdx.x*128;
    const int tid = threadIdx.x;
    const int wid = tid>>5, lane = tid&31;
    const int wm = (wid&1)*64, wn = (wid>>1)*32;
    const int r = lane>>2, cp = lane&3;
    const int arow = tid>>1, akq = (tid&1)*8;          // A (and TB-B): 128 rows x 16 k
    const int bk = tid>>4, bn = (tid&15)*8;            // NN-B: 16 k x 128 n

    float acc[16][4];
    #pragma unroll
    for (int i=0;i<16;i++){ acc[i][0]=0.f; acc[i][1]=0.f; acc[i][2]=0.f; acc[i][3]=0.f; }

    const int nk = K >> 4;

    auto ldA = [&](int kb, uint4* v){
        const unsigned* p = A + (long long)(m0+arow)*lda + kb + akq;
        v[0] = *reinterpret_cast<const uint4*>(p);
        v[1] = *reinterpret_cast<const uint4*>(p+4);
    };
    auto stA = [&](const uint4* v, int s){
        const unsigned* f = reinterpret_cast<const unsigned*>(v);
        #pragma unroll
        for (int j=0;j<8;j++) As[s][akq+j][arow] = f[j];
    };
    auto ldB = [&](int kb, uint4* v){
        if (TB){
            int nc = n0 + arow;
            if (nc < Ncols){
                const unsigned* p = B + (long long)nc*ldb + kb + akq;
                v[0] = *reinterpret_cast<const uint4*>(p);
                v[1] = *reinterpret_cast<const uint4*>(p+4);
            } else {
                v[0] = make_uint4(0,0,0,0); v[1] = make_uint4(0,0,0,0);
            }
        } else {
            const unsigned* p = B + (long long)(kb+bk)*ldb + n0 + bn;
            v[0] = *reinterpret_cast<const uint4*>(p);
            v[1] = *reinterpret_cast<const uint4*>(p+4);
        }
    };
    auto stB = [&](const uint4* v, int s){
        const unsigned* f = reinterpret_cast<const unsigned*>(v);
        if (TB){
            #pragma unroll
            for (int j=0;j<8;j++) Bs[s][akq+j][arow] = f[j];
        } else {
            #pragma unroll
            for (int j=0;j<8;j++) Bs[s][bk][bn+j] = f[j];
        }
    };

    uint4 va[2], vb[2];
    ldA(0, va); ldB(0, vb);
    stA(va, 0); stB(vb, 0);
    __syncthreads();
    for (int t=0; t<nk; t++){
        const int s = t & 1;
        const bool has = (t+1 < nk);
        if (has){ ldA((t+1)<<4, va); ldB((t+1)<<4, vb); }
        #pragma unroll
        for (int vk=0; vk<2; vk++){
            const int k8 = vk*8;
            unsigned a[4][4];
            #pragma unroll
            for (int i=0;i<4;i++){
                int mb = wm + i*16;
                a[i][0] = As[s][k8+cp][mb+r];
                a[i][1] = As[s][k8+cp][mb+r+8];
                a[i][2] = As[s][k8+cp+4][mb+r];
                a[i][3] = As[s][k8+cp+4][mb+r+8];
            }
            unsigned w0[4], w1[4];
            #pragma unroll
            for (int j=0;j<4;j++){
                w0[j] = Bs[s][k8+cp][wn+j*8+r];
                w1[j] = Bs[s][k8+cp+4][wn+j*8+r];
            }
            #pragma unroll
            for (int i=0;i<4;i++)
                #pragma unroll
                for (int j=0;j<4;j++){
                    mma16816(acc[i*4+j], a[i],
                             __byte_perm(w0[j], 0, 0x1010), __byte_perm(w1[j], 0, 0x1010));
                    mma16816(acc[i*4+j], a[i], w0[j]>>16, w1[j]>>16);
                }
        }
        __syncthreads();
        if (has){ stA(va, s^1); stB(vb, s^1); __syncthreads(); }
    }
    #pragma unroll
    for (int i=0;i<4;i++){
        #pragma unroll
        for (int j=0;j<4;j++){
            const float* c = acc[i*4+j];
            int row = m0 + wm + i*16 + r;
            int col = n0 + wn + j*8 + 2*cp;
            if (col < Ncols){
                float v0 = alpha*c[0], v1 = alpha*c[1];
                float v2 = alpha*c[2], v3 = alpha*c[3];
                *reinterpret_cast<float2*>(C + (long long)row*ldc + col) = make_float2(v0,v1);
                *reinterpret_cast<float2*>(C + (long long)(row+8)*ldc + col) = make_float2(v2,v3);
                if (Cp){
                    Cp[(long long)row*ldc + col]   = packhl(v0);
                    Cp[(long long)row*ldc + col+1] = packhl(v1);
                    Cp[(long long)(row+8)*ldc + col]   = packhl(v2);
                    Cp[(long long)(row+8)*ldc + col+1] = packhl(v3);
                }
            }
        }
    }
}

// ---------------- embedding -------------------------------------------------
__global__ void embed_k(const int* __restrict__ ids, const float* __restrict__ emb,
                        const float* __restrict__ pos, float* __restrict__ X, float* __restrict__ H)
{
    int r = blockIdx.x, n = r & (SEQ-1);
    const float* ep = emb + (long long)ids[r]*DM;
    const float* pp = pos + (long long)n*DM;
    for (int d = threadIdx.x; d < DM; d += 256){
        float v = ep[d] + pp[d];
        X[(long long)r*DM+d] = v; H[(long long)r*DM+d] = v;
    }
}

// ---------------- scan layer: LN + z/a projections --------------------------
__global__ void __launch_bounds__(256)
lnproj_k(const float* __restrict__ H, const float* __restrict__ Win, const float* __restrict__ Wg,
         const float* __restrict__ gam, const float* __restrict__ bet,
         float* __restrict__ bufZ, float* __restrict__ bufA)
{
    __shared__ float sX[32][64];
    __shared__ float sW[64*128];
    const int c = blockIdx.x, r0 = blockIdx.y*32, tid = threadIdx.x;
    for (int i=tid;i<32*64;i+=256){
        int row=i>>6, d=i&63;
        sX[row][d] = H[(((long long)(r0+row))*CC+c)*DC+d];
    }
    __syncthreads();
    const int w = tid>>5, lane = tid&31;
    for (int row=w; row<32; row+=8){
        float x0=sX[row][lane], x1=sX[row][lane+32];
        float sm=x0+x1;
        #pragma unroll
        for (int o=16;o;o>>=1) sm += __shfl_xor_sync(0xffffffffu, sm, o);
        float mu = sm*(1.f/64.f);
        float d0=x0-mu, d1=x1-mu;
        float vs=d0*d0+d1*d1;
        #pragma unroll
        for (int o=16;o;o>>=1) vs += __shfl_xor_sync(0xffffffffu, vs, o);
        float inv = rsqrtf(vs*(1.f/64.f)+1e-5f);
        sX[row][lane]    = d0*inv*gam[lane]   +bet[lane];
        sX[row][lane+32] = d1*inv*gam[lane+32]+bet[lane+32];
    }
    __syncthreads();
    for (int i=tid;i<64*128/4;i+=256)
        reinterpret_cast<float4*>(sW)[i] = reinterpret_cast<const float4*>(Win + c*64*128)[i];
    __syncthreads();
    for (int qd=tid; qd<1024; qd+=256){
        int row=qd>>5, e0=(qd&31)<<2;
        float4 a=make_float4(0,0,0,0);
        #pragma unroll 8
        for (int d=0;d<64;d++){
            float xv=sX[row][d];
            float4 wv=*reinterpret_cast<const float4*>(&sW[d*128+e0]);
            a.x=fmaf(xv,wv.x,a.x); a.y=fmaf(xv,wv.y,a.y); a.z=fmaf(xv,wv.z,a.z); a.w=fmaf(xv,wv.w,a.w);
        }
        *reinterpret_cast<float4*>(&bufZ[(((long long)(r0+row))*CC+c)*EE+e0]) = a;
    }
    __syncthreads();
    for (int i=tid;i<64*128/4;i+=256)
        reinterpret_cast<float4*>(sW)[i] = reinterpret_cast<const float4*>(Wg + c*64*128)[i];
    __syncthreads();
    for (int qd=tid; qd<1024; qd+=256){
        int row=qd>>5, e0=(qd&31)<<2;
        float4 a=make_float4(0,0,0,0);
        #pragma unroll 8
        for (int d=0;d<64;d++){
            float xv=sX[row][d];
            float4 wv=*reinterpret_cast<const float4*>(&sW[d*128+e0]);
            a.x=fmaf(xv,wv.x,a.x); a.y=fmaf(xv,wv.y,a.y); a.z=fmaf(xv,wv.z,a.z); a.w=fmaf(xv,wv.w,a.w);
        }
        a.x=sigm(a.x); a.y=sigm(a.y); a.z=sigm(a.z); a.w=sigm(a.w);
        *reinterpret_cast<float4*>(&bufA[(((long long)(r0+row))*CC+c)*EE+e0]) = a;
    }
}

// ---------------- gated recurrence over time --------------------------------
__global__ void scan_k(float* __restrict__ Z, const float* __restrict__ A)
{
    int ch = blockIdx.x*256 + threadIdx.x;
    const int str = CC*EE;
    long long p = (long long)(ch>>11)*((long long)SEQ*str) + (ch & (str-1));
    float h = 0.f;
    for (int n=0;n<SEQ;n+=4){
        float z0=Z[p], z1=Z[p+str], z2=Z[p+2*str], z3=Z[p+3*str];
        float a0=A[p], a1=A[p+str], a2=A[p+2*str], a3=A[p+3*str];
        h = fmaf(a0, h-z0, z0); Z[p]=h;
        h = fmaf(a1, h-z1, z1); Z[p+str]=h;
        h = fmaf(a2, h-z2, z2); Z[p+2*str]=h;
        h = fmaf(a3, h-z3, z3); Z[p+3*str]=h;
        p += 4*str;
    }
}

// ---------------- scan output projection + residual -------------------------
__global__ void __launch_bounds__(256)
outproj_k(const float* __restrict__ hbuf, const float* __restrict__ Wout, float* __restrict__ H)
{
    __shared__ float sh[16][128];
    __shared__ float sW[128*64];
    const int c = blockIdx.x, r0 = blockIdx.y*16, tid = threadIdx.x;
    for (int i=tid;i<16*128/4;i+=256){
        int row=i>>5, e0=(i&31)<<2;
        *reinterpret_cast<float4*>(&sh[row][e0]) =
            *reinterpret_cast<const float4*>(&hbuf[(((long long)(r0+row))*CC+c)*EE+e0]);
    }
    for (int i=tid;i<128*64/4;i+=256)
        reinterpret_cast<float4*>(sW)[i] = reinterpret_cast<const float4*>(Wout + c*128*64)[i];
    __syncthreads();
    int row = tid>>4, d0 = (tid&15)<<2;
    float4 a=make_float4(0,0,0,0);
    #pragma unroll 8
    for (int e=0;e<128;e++){
        float hv=sh[row][e];
        float4 wv=*reinterpret_cast<const float4*>(&sW[e*64+d0]);
        a.x=fmaf(hv,wv.x,a.x); a.y=fmaf(hv,wv.y,a.y); a.z=fmaf(hv,wv.z,a.z); a.w=fmaf(hv,wv.w,a.w);
    }
    long long o = (((long long)(r0+row))*CC+c)*DC+d0;
    float4 h0 = *reinterpret_cast<const float4*>(&H[o]);
    a.x+=h0.x; a.y+=h0.y; a.z+=h0.z; a.w+=h0.w;
    *reinterpret_cast<float4*>(&H[o]) = a;
}

// ---------------- PCM -------------------------------------------------------
__global__ void __launch_bounds__(256)
pcm_k(float* __restrict__ H, const float* __restrict__ X, const float* __restrict__ Wpred,
      float* __restrict__ surp, float* __restrict__ auxp)
{
    __shared__ float sH[32][64];
    __shared__ float sW[64*64];
    __shared__ float sred[32];
    const int c = blockIdx.x, r0 = blockIdx.y*32, tid = threadIdx.x;
    for (int i=tid;i<32*64;i+=256){
        int row=i>>6, d=i&63;
        sH[row][d] = H[(((long long)(r0+row))*CC+c)*DC+d];
    }
    for (int i=tid;i<64*64/4;i+=256)
        reinterpret_cast<float4*>(sW)[i] = reinterpret_cast<const float4*>(Wpred + c*64*64)[i];
    __syncthreads();
    float auxa = 0.f;
    for (int qd=tid; qd<512; qd+=256){
        int row=qd>>4, d0=(qd&15)<<2;
        float4 a=make_float4(0,0,0,0);
        #pragma unroll 8
        for (int d=0;d<64;d++){
            float hv=sH[row][d];
            float4 wv=*reinterpret_cast<const float4*>(&sW[d*64+d0]);
            a.x=fmaf(hv,wv.x,a.x); a.y=fmaf(hv,wv.y,a.y); a.z=fmaf(hv,wv.z,a.z); a.w=fmaf(hv,wv.w,a.w);
        }
        long long gi = (((long long)(r0+row))*CC+c)*DC+d0;
        float4 xv = *reinterpret_cast<const float4*>(&X[gi]);
        float dx=a.x-xv.x, dy=a.y-xv.y, dz=a.z-xv.z, dw=a.w-xv.w;
        auxa += dx*dx+dy*dy+dz*dz+dw*dw;
        float4 sp = make_float4(fabsf(dx),fabsf(dy),fabsf(dz),fabsf(dw));
        *reinterpret_cast<float4*>(&surp[gi]) = sp;
        float4 hn;
        hn.x = sH[row][d0+0]*(1.f+tanhf(sp.x));
        hn.y = sH[row][d0+1]*(1.f+tanhf(sp.y));
        hn.z = sH[row][d0+2]*(1.f+tanhf(sp.z));
        hn.w = sH[row][d0+3]*(1.f+tanhf(sp.w));
        *reinterpret_cast<float4*>(&H[gi]) = hn;
    }
    float tot = blockSum256(auxa, sred);
    if (tid==0) auxp[blockIdx.y*CC + c] = tot;
}

// ---------------- seed & w_cand (float + packed wc) -------------------------
__global__ void __launch_bounds__(256)
seedw_k(const float* __restrict__ H, const float* __restrict__ Ws, const float* __restrict__ Ww,
        float* __restrict__ seed, float* __restrict__ wc, unsigned* __restrict__ wcp)
{
    __shared__ float sH[32][64];
    __shared__ float sWa[64*64];
    __shared__ float sWb[64*64];
    const int c = blockIdx.x, r0 = blockIdx.y*32, tid = threadIdx.x;
    for (int i=tid;i<32*64;i+=256){
        int row=i>>6, d=i&63;
        sH[row][d] = H[(((long long)(r0+row))*CC+c)*DC+d];
    }
    for (int i=tid;i<64*64/4;i+=256){
        reinterpret_cast<float4*>(sWa)[i] = reinterpret_cast<const float4*>(Ws + c*64*64)[i];
        reinterpret_cast<float4*>(sWb)[i] = reinterpret_cast<const float4*>(Ww + c*64*64)[i];
    }
    __syncthreads();
    for (int qd=tid; qd<512; qd+=256){
        int row=qd>>4, d0=(qd&15)<<2;
        float4 a=make_float4(0,0,0,0), b=make_float4(0,0,0,0);
        #pragma unroll 8
        for (int d=0;d<64;d++){
            float hv=sH[row][d];
            float4 wa=*reinterpret_cast<const float4*>(&sWa[d*64+d0]);
            float4 wb=*reinterpret_cast<const float4*>(&sWb[d*64+d0]);
            a.x=fmaf(hv,wa.x,a.x); a.y=fmaf(hv,wa.y,a.y); a.z=fmaf(hv,wa.z,a.z); a.w=fmaf(hv,wa.w,a.w);
            b.x=fmaf(hv,wb.x,b.x); b.y=fmaf(hv,wb.y,b.y); b.z=fmaf(hv,wb.z,b.z); b.w=fmaf(hv,wb.w,b.w);
        }
        long long gi = (((long long)(r0+row))*CC+c)*DC+d0;
        *reinterpret_cast<float4*>(&seed[gi]) = a;
        *reinterpret_cast<float4*>(&wc[gi]) = b;
        *reinterpret_cast<uint4*>(&wcp[gi]) = packhl4(b);
    }
}

// ---------------- per-row stats ---------------------------------------------
__global__ void __launch_bounds__(256)
rowstat_k(const float* __restrict__ surp, const float* __restrict__ wc,
          const float* __restrict__ Hf, const float* __restrict__ Wnv,
          const float* __restrict__ Wnb, float* __restrict__ smg,
          float* __restrict__ wiv, float* __restrict__ wnv)
{
    __shared__ float sred[32];
    const int r = blockIdx.x, tid = threadIdx.x;
    long long base = (long long)r*DM + tid*4;
    float4 sv = *reinterpret_cast<const float4*>(surp + base);
    float4 wv = *reinterpret_cast<const float4*>(wc + base);
    float4 hv = *reinterpret_cast<const float4*>(Hf + base);
    float s1 = sv.x+sv.y+sv.z+sv.w;
    float s2 = wv.x*wv.x+wv.y*wv.y+wv.z*wv.z+wv.w*wv.w;
    float t1 = blockSum256(s1, sred);
    if (tid==0) smg[r] = sigm(t1*(1.f/(float)DM));
    float t2 = blockSum256(s2, sred);
    if (tid==0) wiv[r] = 1.f/(sqrtf(t2)+1e-6f);
    float acc[NBK];
    #pragma unroll
    for (int b=0;b<NBK;b++) acc[b]=0.f;
    float hvv[4] = {hv.x,hv.y,hv.z,hv.w};
    #pragma unroll
    for (int j=0;j<4;j++){
        const float* wr = Wnv + (tid*4+j)*NBK;
        #pragma unroll
        for (int b=0;b<NBK;b++) acc[b] = fmaf(hvv[j], wr[b], acc[b]);
    }
    #pragma unroll
    for (int b=0;b<NBK;b++){
        float t = blockSum256(acc[b], sred);
        if (tid==0) wnv[r*NBK+b] = sigm(t + Wnb[b]);
    }
}

// ---------------- em_K inverse norms ----------------------------------------
__global__ void knorm_k(const float* __restrict__ emK, float* __restrict__ kiv)
{
    __shared__ float sred[32];
    const int row = blockIdx.x;
    float4 v = *reinterpret_cast<const float4*>(emK + (long long)row*DM + threadIdx.x*4);
    float s = v.x*v.x+v.y*v.y+v.z*v.z+v.w*v.w;
    float t = blockSum256(s, sred);
    if (threadIdx.x==0) kiv[row] = 1.f/(sqrtf(t)+1e-6f);
}

// ---------------- cumsum over time (in-place float) -------------------------
__global__ void cumsum_k(float* __restrict__ X)
{
    int ch = blockIdx.x*256 + threadIdx.x;
    long long p = (long long)(ch>>10)*((long long)SEQ*DM) + (ch & (DM-1));
    float h = 0.f;
    for (int n=0;n<SEQ;n+=4){
        float v0=X[p], v1=X[p+DM], v2=X[p+2*DM], v3=X[p+3*DM];
        h+=v0; X[p]=h; h+=v1; X[p+DM]=h; h+=v2; X[p+2*DM]=h; h+=v3; X[p+3*DM]=h;
        p += 4*DM;
    }
}

// ---------------- cumsum over time -> packed output -------------------------
__global__ void cumsum_pack_k(const float* __restrict__ X, unsigned* __restrict__ P)
{
    int ch = blockIdx.x*256 + threadIdx.x;
    long long p = (long long)(ch>>10)*((long long)SEQ*DM) + (ch & (DM-1));
    float h = 0.f;
    for (int n=0;n<SEQ;n+=4){
        h += X[p];        P[p]       = packhl(h);
        h += X[p+DM];     P[p+DM]    = packhl(h);
        h += X[p+2*DM];   P[p+2*DM]  = packhl(h);
        h += X[p+3*DM];   P[p+3*DM]  = packhl(h);
        p += 4*DM;
    }
}

// ---------------- pm sigmoid-sum epilogue -----------------------------------
__global__ void pmsum_k(const float* __restrict__ dpm, const float* __restrict__ pmst,
                        float* __restrict__ pms)
{
    const int r = blockIdx.x, s = r >> 10;
    for (int d = threadIdx.x; d < DM; d += 256){
        float acc = 0.f;
        #pragma unroll
        for (int b=0;b<NBK;b++)
            acc += sigm(pmst[((long long)s*NBK+b)*DM+d] + dpm[((long long)b*NR + r)*DM + d]);
        pms[(long long)r*DM+d] = acc;
    }
}

// ---------------- novelty -> summed write gate ------------------------------
__global__ void novel_k(const float* __restrict__ sim, const float* __restrict__ wnv,
                        const float* __restrict__ smg, const float* __restrict__ wiv,
                        const float* __restrict__ kiv, float* __restrict__ nvs)
{
    __shared__ float snov[NBK];
    const int r = blockIdx.x, s = r >> 10, n = r & (SEQ-1);
    const int b = threadIdx.x >> 5, lane = threadIdx.x & 31;
    const int z = s*NBK + b;
    const float* sp = sim + ((long long)z*SEQ + n)*MS;
    const float* kp = kiv + z*MS;
    float m = fmaxf(sp[lane]*kp[lane], sp[lane+32]*kp[lane+32]);
    #pragma unroll
    for (int o=16;o;o>>=1) m = fmaxf(m, __shfl_xor_sync(0xffffffffu, m, o));
    if (lane==0){
        float msim = m * wiv[r];
        snov[b] = wnv[r*NBK+b] * smg[r] * fmaxf(0.f, 1.f - msim);
    }
    __syncthreads();
    if (threadIdx.x==0){
        float t=0.f;
        #pragma unroll
        for (int i=0;i<NBK;i++) t += snov[i];
        nvs[r] = t;
    }
}

__global__ void cem_k(const float* __restrict__ nvs, const float* __restrict__ wc,
                      float* __restrict__ cem)
{
    const int r = blockIdx.x;
    float nv = nvs[r];
    long long base = (long long)r*DM + threadIdx.x*4;
    float4 v = *reinterpret_cast<const float4*>(wc + base);
    v.x*=nv; v.y*=nv; v.z*=nv; v.w*=nv;
    *reinterpret_cast<float4*>(cem + base) = v;
}

// ---------------- trail attention pieces ------------------------------------
__global__ void qinit_k(const float* __restrict__ seed, unsigned* __restrict__ qp)
{
    long long f = (long long)blockIdx.x*256 + threadIdx.x;
    const long long per = (long long)SEQ*DM/4;
    for (int it=0; it<4; it++, f += (long long)8192*256){
        long long z = f / per, rem = f - z*per;
        long long s = z >> 3;
        reinterpret_cast<uint4*>(qp)[f] =
            packhl4(reinterpret_cast<const float4*>(seed)[s*per + rem]);
    }
}

__global__ void softmax_k(const float* __restrict__ sim, unsigned* __restrict__ simp)
{
    const int row = blockIdx.x*8 + (threadIdx.x>>5);
    const int lane = threadIdx.x & 31;
    const float* p = sim + (long long)row*MS;
    unsigned* q = simp + (long long)row*MS;
    const float scale = 0.03125f;
    float a = p[lane]*scale, b = p[lane+32]*scale;
    float m = fmaxf(a,b);
    #pragma unroll
    for (int o=16;o;o>>=1) m = fmaxf(m, __shfl_xor_sync(0xffffffffu, m, o));
    float ea = expf(a-m), eb = expf(b-m);
    float s = ea+eb;
    #pragma unroll
    for (int o=16;o;o>>=1) s += __shfl_xor_sync(0xffffffffu, s, o);
    float inv = 1.f/s;
    q[lane] = packhl(ea*inv); q[lane+32] = packhl(eb*inv);
}

// ---------------- integrate reads -------------------------------------------
__global__ void integrate_k(const float* __restrict__ Hf, const float* __restrict__ pms,
                            const float* __restrict__ q, const float* __restrict__ cem,
                            float* __restrict__ out)
{
    const int r = blockIdx.x, s = r >> 10, n = r & (SEQ-1);
    long long base = (long long)r*DM + threadIdx.x*4;
    float4 hv = *reinterpret_cast<const float4*>(Hf + base);
    float4 pv = *reinterpret_cast<const float4*>(pms + base);
    float4 cv = *reinterpret_cast<const float4*>(cem + base);
    float4 a;
    a.x = hv.x*pv.x + cv.x; a.y = hv.y*pv.y + cv.y;
    a.z = hv.z*pv.z + cv.z; a.w = hv.w*pv.w + cv.w;
    #pragma unroll
    for (int b=0;b<NBK;b++){
        float4 qv = *reinterpret_cast<const float4*>(
            q + (((long long)(s*NBK+b))*SEQ + n)*DM + threadIdx.x*4);
        a.x += qv.x; a.y += qv.y; a.z += qv.z; a.w += qv.w;
    }
    *reinterpret_cast<float4*>(out + base) = a;
}

// ---------------- final LN -> packed lno ------------------------------------
__global__ void finalln_k(const float* __restrict__ X, const float* __restrict__ g,
                          const float* __restrict__ b, unsigned* __restrict__ O)
{
    __shared__ float sred[32];
    const int r = blockIdx.x, tid = threadIdx.x;
    long long base = (long long)r*DM + tid*4;
    float4 v = *reinterpret_cast<const float4*>(X + base);
    float s1 = v.x+v.y+v.z+v.w;
    float mu = blockSum256(s1, sred)*(1.f/(float)DM);
    float dx=v.x-mu, dy=v.y-mu, dz=v.z-mu, dw=v.w-mu;
    float s2 = dx*dx+dy*dy+dz*dz+dw*dw;
    float inv = rsqrtf(blockSum256(s2, sred)*(1.f/(float)DM) + 1e-5f);
    float4 gv = *reinterpret_cast<const float4*>(g + tid*4);
    float4 bv = *reinterpret_cast<const float4*>(b + tid*4);
    float4 o;
    o.x = dx*inv*gv.x+bv.x; o.y = dy*inv*gv.y+bv.y;
    o.z = dz*inv*gv.z+bv.z; o.w = dw*inv*gv.w+bv.w;
    *reinterpret_cast<uint4*>(O + base) = packhl4(o);
}

__global__ void auxfin_k(const float* __restrict__ auxp, float* __restrict__ out)
{
    __shared__ float sred[32];
    float a = 0.f;
    for (int i = threadIdx.x; i < 2048; i += 256) a += auxp[i];
    float t = blockSum256(a, sred);
    if (threadIdx.x==0) out[LOGN] = t * (0.1f/((float)NR*(float)DM));
}

// ---------------- host ------------------------------------------------------
extern "C" void kernel_launch(void* const* d_in, const int* in_sizes, int n_in,
                              void* d_out, int out_size)
{
    const int*   ids   = (const int*)  d_in[0];
    const float* emb   = (const float*)d_in[1];
    const float* pos   = (const float*)d_in[2];
    const float* s1Win = (const float*)d_in[3];
    const float* s1Wg  = (const float*)d_in[4];
    const float* s1Wo  = (const float*)d_in[5];
    const float* s1g   = (const float*)d_in[6];
    const float* s1b   = (const float*)d_in[7];
    const float* s3Win = (const float*)d_in[8];
    const float* s3Wg  = (const float*)d_in[9];
    const float* s3Wo  = (const float*)d_in[10];
    const float* s3g   = (const float*)d_in[11];
    const float* s3b   = (const float*)d_in[12];
    const float* Wseed = (const float*)d_in[13];
    const float* Ww    = (const float*)d_in[14];
    const float* Wpred = (const float*)d_in[15];
    const float* Wnv   = (const float*)d_in[16];
    const float* Wnb   = (const float*)d_in[17];
    const float* Wdel  = (const float*)d_in[18];
    const float* pmst  = (const float*)d_in[19];
    const float* emK   = (const float*)d_in[20];
    const float* emV   = (const float*)d_in[21];
    const float* lng   = (const float*)d_in[22];
    const float* lnb   = (const float*)d_in[23];
    float* out = (float*)d_out;

    float *X,*H,*bZ,*bA,*S,*seed,*wc,*pms,*dpm,*q,*sim;
    float *wnv,*smg,*nvs,*wiv,*kiv,*auxp;
    unsigned *pemb,*pwdel,*plno,*pS,*pwc,*pemK,*pemV,*pq,*psim;
    cudaGetSymbolAddress((void**)&X, g_X);
    cudaGetSymbolAddress((void**)&H, g_H);
    cudaGetSymbolAddress((void**)&bZ, g_bufZ);
    cudaGetSymbolAddress((void**)&bA, g_bufA);
    cudaGetSymbolAddress((void**)&S, g_surp);
    cudaGetSymbolAddress((void**)&seed, g_seed);
    cudaGetSymbolAddress((void**)&wc, g_wc);
    cudaGetSymbolAddress((void**)&pms, g_pms);
    cudaGetSymbolAddress((void**)&dpm, g_dpm);
    cudaGetSymbolAddress((void**)&q, g_q);
    cudaGetSymbolAddress((void**)&sim, g_sim);
    cudaGetSymbolAddress((void**)&wnv, g_wnv);
    cudaGetSymbolAddress((void**)&smg, g_smg);
    cudaGetSymbolAddress((void**)&nvs, g_nvs);
    cudaGetSymbolAddress((void**)&wiv, g_wiv);
    cudaGetSymbolAddress((void**)&kiv, g_kiv);
    cudaGetSymbolAddress((void**)&auxp, g_aux);
    cudaGetSymbolAddress((void**)&pemb, p_emb);
    cudaGetSymbolAddress((void**)&pwdel, p_wdel);
    cudaGetSymbolAddress((void**)&plno, p_lno);
    cudaGetSymbolAddress((void**)&pS, p_S);
    cudaGetSymbolAddress((void**)&pwc, p_wc);
    cudaGetSymbolAddress((void**)&pemK, p_emK);
    cudaGetSymbolAddress((void**)&pemV, p_emV);
    cudaGetSymbolAddress((void**)&pq, p_q);
    cudaGetSymbolAddress((void**)&psim, p_sim);

    const long long sND = (long long)SEQ*DM;
    const long long sMD = (long long)MS*DM;
    const long long sNM = (long long)SEQ*MS;

    // pack constants
    pack_k<<<2048,256>>>(emb, pemb, (long long)VOC*DM/4);
    pack_k<<<1024,256>>>(Wdel, pwdel, (long long)NBK*DM*DM/4);
    pack_k<<<256,256>>>(emK, pemK, (long long)BSZ*NBK*MS*DM/4);
    pack_k<<<256,256>>>(emV, pemV, (long long)BSZ*NBK*MS*DM/4);

    embed_k<<<NR,256>>>(ids, emb, pos, X, H);

    for (int l=0;l<2;l++){
        lnproj_k<<<dim3(CC,NR/32),256>>>(H, s1Win+l*CC*DC*EE, s1Wg+l*CC*DC*EE,
                                         s1g+l*DC, s1b+l*DC, bZ, bA);
        scan_k<<<32,256>>>(bZ, bA);
        outproj_k<<<dim3(CC,NR/16),256>>>(bZ, s1Wo+l*CC*EE*DC, H);
    }

    pcm_k<<<dim3(CC,NR/32),256>>>(H, X, Wpred, S, auxp);
    seedw_k<<<dim3(CC,NR/32),256>>>(H, Wseed, Ww, seed, wc, pwc);
    rowstat_k<<<NR,256>>>(S, wc, H, Wnv, Wnb, smg, wiv, wnv);
    knorm_k<<<BSZ*NBK*MS,256>>>(emK, kiv);

    // similarity: w_cand @ em_K^T per (s,b)
    hgemm_k<true><<<dim3(1,SEQ/128,BSZ*NBK),256>>>(pwc, pemK, sim, (unsigned*)0,
        SEQ, MS, DM, DM, DM, MS, sND, sMD, sNM, NBK, 1.f);
    novel_k<<<NR,256>>>(sim, wnv, smg, wiv, kiv, nvs);
    cem_k<<<NR,256>>>(nvs, wc, bZ);
    cumsum_k<<<16,256>>>(bZ);

    // procedural memory: packed cumsum(surp) then 8 batched GEMMs vs W_delta
    cumsum_pack_k<<<16,256>>>(S, pS);
    hgemm_k<false><<<dim3(DM/128,NR/128,NBK),256>>>(pS, pwdel, dpm, (unsigned*)0,
        NR, DM, DM, DM, DM, DM, 0, (long long)DM*DM, (long long)NR*DM, NBK, 1.f);
    pmsum_k<<<NR,256>>>(dpm, pmst, pms);

    // trail attention
    qinit_k<<<8192,256>>>(seed, pq);
    for (int t=0;t<4;t++){
        hgemm_k<true><<<dim3(1,SEQ/128,BSZ*NBK),256>>>(pq, pemK, sim, (unsigned*)0,
            SEQ, MS, DM, DM, DM, MS, sND, sMD, sNM, 1, 1.f);
        softmax_k<<<BSZ*NBK*SEQ/8,256>>>(sim, psim);
        hgemm_k<false><<<dim3(DM/128,SEQ/128,BSZ*NBK),256>>>(psim, pemV, q, pq,
            SEQ, DM, MS, MS, DM, DM, sNM, sMD, sND, 1, 1.f);
    }

    integrate_k<<<NR,256>>>(H, pms, q, bZ, X);

    for (int l=0;l<2;l++){
        lnproj_k<<<dim3(CC,NR/32),256>>>(X, s3Win+l*CC*DC*EE, s3Wg+l*CC*DC*EE,
                                         s3g+l*DC, s3b+l*DC, bZ, bA);
        scan_k<<<32,256>>>(bZ, bA);
        outproj_k<<<dim3(CC,NR/16),256>>>(bZ, s3Wo+l*CC*EE*DC, X);
    }

    finalln_k<<<NR,256>>>(X, lng, lnb, plno);

    // logits: lno [4096,1024] @ emb^T [1024,32000]
    hgemm_k<true><<<dim3(VOC/128,NR/128,1),256>>>(plno, pemb, out, (unsigned*)0,
        NR, VOC, DM, DM, DM, VOC, 0, 0, 0, 1, 1.f);

    if ((long long)out_size > LOGN)
        auxfin_k<<<1,256>>>(auxp, out);
}

// round 12
// speedup vs baseline: 1.6604x; 1.2591x over previous
#include <cuda_runtime.h>
#include <cuda_bf16.h>
#include <stdint.h>
#include <math.h>

#define BSZ 4
#define SEQ 1024
#define VOC 32000
#define DM 1024
#define CC 16
#define DC 64
#define NBK 8
#define MS 64
#define EE 128
#define NR (BSZ*SEQ)
#define LOGN ((long long)NR*VOC)

// ---------------- float scratch ----------------------------------------------
__device__ float g_X[NR*DM];
__device__ float g_H[NR*DM];
__device__ float g_bufZ[NR*CC*EE];
__device__ float g_bufA[NR*CC*EE];
__device__ float g_surp[NR*DM];
__device__ float g_seed[NR*DM];
__device__ float g_wc[NR*DM];
__device__ float g_pms[NR*DM];
__device__ float g_dpm[(long long)NBK*NR*DM];
__device__ float g_q[(long long)BSZ*NBK*SEQ*DM];
__device__ float g_sim[(long long)BSZ*NBK*SEQ*MS];
__device__ float g_wnv[NR*NBK];
__device__ float g_smg[NR];
__device__ float g_nvs[NR];
__device__ float g_wiv[NR];
__device__ float g_kiv[BSZ*NBK*MS];
__device__ float g_aux[2048];

// ---------------- packed (hi-bf16 | lo-bf16) operand buffers ------------------
__device__ unsigned p_emb[(long long)VOC*DM];
__device__ unsigned p_wdel[(long long)NBK*DM*DM];
__device__ unsigned p_lno[NR*DM];
__device__ unsigned p_S[NR*DM];
__device__ unsigned p_wc[NR*DM];
__device__ unsigned p_emK[BSZ*NBK*MS*DM];
__device__ unsigned p_emV[BSZ*NBK*MS*DM];
__device__ unsigned p_q[(long long)BSZ*NBK*SEQ*DM];
__device__ unsigned p_sim[(long long)BSZ*NBK*SEQ*MS];

__device__ __forceinline__ float sigm(float x){ return 1.f/(1.f+expf(-x)); }

__device__ __forceinline__ unsigned packhl(float x){
    __nv_bfloat16 h = __float2bfloat16(x);
    float hf = __bfloat162float(h);
    __nv_bfloat16 l = __float2bfloat16(x - hf);
    return (unsigned)__bfloat16_as_ushort(h) | ((unsigned)__bfloat16_as_ushort(l) << 16);
}
__device__ __forceinline__ uint4 packhl4(float4 v){
    uint4 o; o.x=packhl(v.x); o.y=packhl(v.y); o.z=packhl(v.z); o.w=packhl(v.w); return o;
}

__device__ __forceinline__ float blockSum256(float v, float* sred){
    __syncthreads();
    int lane = threadIdx.x & 31, w = threadIdx.x >> 5;
    #pragma unroll
    for (int o=16;o;o>>=1) v += __shfl_xor_sync(0xffffffffu, v, o);
    if (lane==0) sred[w]=v;
    __syncthreads();
    float t = (threadIdx.x<8)? sred[threadIdx.x] : 0.f;
    if (w==0){
        #pragma unroll
        for (int o=4;o;o>>=1) t += __shfl_xor_sync(0xffffffffu, t, o);
        if (lane==0) sred[0]=t;
    }
    __syncthreads();
    return sred[0];
}

// ---------------- generic pack kernel ----------------------------------------
__global__ void pack_k(const float* __restrict__ in, unsigned* __restrict__ out, long long n4)
{
    long long i = (long long)blockIdx.x*256 + threadIdx.x;
    long long str = (long long)gridDim.x*256;
    for (; i < n4; i += str)
        reinterpret_cast<uint4*>(out)[i] = packhl4(reinterpret_cast<const float4*>(in)[i]);
}

// ---------------- tensor-core GEMM on pre-packed operands --------------------
// C[z] = alpha * A[z/zdivA] * op(B[z]).  TB: B row-major [Ncols,K] (uses B^T).
// A,B packed u32 (hi|lo bf16). M%128==0, K%16==0. Ncols guarded.
__device__ __forceinline__ unsigned s2u(const void* p){
    unsigned a; asm("{ .reg .u64 t; cvta.to.shared.u64 t, %1; cvt.u32.u64 %0, t; }" : "=r"(a) : "l"(p));
    return a;
}
__device__ __forceinline__ void mma16816(float* c, const unsigned* a, unsigned b0, unsigned b1){
    asm volatile("mma.sync.aligned.m16n8k16.row.col.f32.bf16.bf16.f32 "
        "{%0,%1,%2,%3}, {%4,%5,%6,%7}, {%8,%9}, {%0,%1,%2,%3};"
        : "+f"(c[0]), "+f"(c[1]), "+f"(c[2]), "+f"(c[3])
        : "r"(a[0]), "r"(a[1]), "r"(a[2]), "r"(a[3]), "r"(b0), "r"(b1));
}
__device__ __forceinline__ void ldsm4(unsigned& r0, unsigned& r1, unsigned& r2, unsigned& r3, unsigned addr){
    asm volatile("ldmatrix.sync.aligned.m8n8.x4.shared.b16 {%0,%1,%2,%3}, [%4];"
        : "=r"(r0), "=r"(r1), "=r"(r2), "=r"(r3) : "r"(addr));
}

// smem layout: per buffer s (s=0,1): A tile rows[128] x 20 u32, then B tile same.
// words per tile = 2560; per buffer = 5120; total = 10240 u32 = 40960 B.
template<bool TB>
__global__ void __launch_bounds__(256,2)
hgemm_k(const unsigned* __restrict__ Ag, const unsigned* __restrict__ Bg,
        float* __restrict__ Cg, unsigned* __restrict__ Cpg,
        int M, int Ncols, int K, int lda, int ldb, int ldc,
        long long sA, long long sB, long long sC, int zdivA, float alpha)
{
    __shared__ unsigned smem[10240];
    const int z = blockIdx.z;
    const unsigned* A = Ag + (long long)(z/zdivA)*sA;
    const unsigned* B = Bg + (long long)z*sB;
    float* C = Cg + (long long)z*sC;
    unsigned* Cp = Cpg ? (Cpg + (long long)z*sC) : (unsigned*)0;
    const int m0 = blockIdx.y*128, n0 = blockIdx.x*128;
    const int tid = threadIdx.x;
    const int wid = tid>>5, lane = tid&31;
    const int wm = (wid&1)*64, wn = (wid>>1)*32;
    const int r = lane>>2, cp = lane&3;
    const int arow = tid>>1, ahalf = tid&1;      // row-staging map (A and TB-B)
    const int bk = tid>>4, bn = (tid&15)*8;      // NN-B staging map

    const unsigned sb = s2u(smem);
    // ldmatrix lane geometry: row-in-tile and word offset
    const int lrow = ((lane>>3)&1)*8 + (lane&7);
    const int lcol = (lane>>4)*4;
    unsigned aFB[4], bFB[2];
    #pragma unroll
    for (int i=0;i<4;i++) aFB[i] = sb + ((wm + i*16 + lrow)*20 + lcol)*4;
    #pragma unroll
    for (int jp=0;jp<2;jp++) bFB[jp] = sb + 10240 + ((wn + jp*16 + lrow)*20 + lcol)*4;

    float acc[16][4];
    #pragma unroll
    for (int i=0;i<16;i++){ acc[i][0]=0.f; acc[i][1]=0.f; acc[i][2]=0.f; acc[i][3]=0.f; }

    const int nk = K >> 4;

    auto ldA = [&](int kb, uint4* v){
        const unsigned* p = A + (long long)(m0+arow)*lda + kb + ahalf*8;
        v[0] = *reinterpret_cast<const uint4*>(p);
        v[1] = *reinterpret_cast<const uint4*>(p+4);
    };
    auto stA = [&](const uint4* v, int s){
        unsigned* d = smem + s*5120 + arow*20 + ahalf*8;
        *reinterpret_cast<uint4*>(d)   = v[0];
        *reinterpret_cast<uint4*>(d+4) = v[1];
    };
    auto ldB = [&](int kb, uint4* v){
        if (TB){
            int nc = n0 + arow;
            if (nc < Ncols){
                const unsigned* p = B + (long long)nc*ldb + kb + ahalf*8;
                v[0] = *reinterpret_cast<const uint4*>(p);
                v[1] = *reinterpret_cast<const uint4*>(p+4);
            } else {
                v[0] = make_uint4(0,0,0,0); v[1] = make_uint4(0,0,0,0);
            }
        } else {
            const unsigned* p = B + (long long)(kb+bk)*ldb + n0 + bn;
            v[0] = *reinterpret_cast<const uint4*>(p);
            v[1] = *reinterpret_cast<const uint4*>(p+4);
        }
    };
    auto stB = [&](const uint4* v, int s){
        unsigned* base = smem + s*5120 + 2560;
        if (TB){
            unsigned* d = base + arow*20 + ahalf*8;
            *reinterpret_cast<uint4*>(d)   = v[0];
            *reinterpret_cast<uint4*>(d+4) = v[1];
        } else {
            const unsigned* f = reinterpret_cast<const unsigned*>(v);
            #pragma unroll
            for (int j=0;j<8;j++) base[(bn+j)*20 + bk] = f[j];
        }
    };

    uint4 va[2], vb[2];
    ldA(0, va); ldB(0, vb);
    stA(va, 0); stB(vb, 0);
    __syncthreads();
    for (int t=0; t<nk; t++){
        const int s = t & 1;
        const bool has = (t+1 < nk);
        if (has){ ldA((t+1)<<4, va); ldB((t+1)<<4, vb); }
        #pragma unroll
        for (int vk=0; vk<2; vk++){
            unsigned a[4][4];
            #pragma unroll
            for (int i=0;i<4;i++)
                ldsm4(a[i][0], a[i][1], a[i][2], a[i][3], aFB[i] + s*20480 + vk*32);
            unsigned w0[4], w1[4];
            #pragma unroll
            for (int jp=0;jp<2;jp++)
                ldsm4(w0[2*jp], w0[2*jp+1], w1[2*jp], w1[2*jp+1], bFB[jp] + s*20480 + vk*32);
            #pragma unroll
            for (int i=0;i<4;i++)
                #pragma unroll
                for (int j=0;j<4;j++){
                    mma16816(acc[i*4+j], a[i],
                             __byte_perm(w0[j], 0, 0x1010), __byte_perm(w1[j], 0, 0x1010));
                    mma16816(acc[i*4+j], a[i], w0[j]>>16, w1[j]>>16);
                }
        }
        if (has){ stA(va, s^1); stB(vb, s^1); }
        __syncthreads();
    }
    #pragma unroll
    for (int i=0;i<4;i++){
        #pragma unroll
        for (int j=0;j<4;j++){
            const float* c = acc[i*4+j];
            int row = m0 + wm + i*16 + r;
            int col = n0 + wn + j*8 + 2*cp;
            if (col < Ncols){
                float v0 = alpha*c[0], v1 = alpha*c[1];
                float v2 = alpha*c[2], v3 = alpha*c[3];
                *reinterpret_cast<float2*>(C + (long long)row*ldc + col) = make_float2(v0,v1);
                *reinterpret_cast<float2*>(C + (long long)(row+8)*ldc + col) = make_float2(v2,v3);
                if (Cp){
                    Cp[(long long)row*ldc + col]   = packhl(v0);
                    Cp[(long long)row*ldc + col+1] = packhl(v1);
                    Cp[(long long)(row+8)*ldc + col]   = packhl(v2);
                    Cp[(long long)(row+8)*ldc + col+1] = packhl(v3);
                }
            }
        }
    }
}

// ---------------- embedding -------------------------------------------------
__global__ void embed_k(const int* __restrict__ ids, const float* __restrict__ emb,
                        const float* __restrict__ pos, float* __restrict__ X, float* __restrict__ H)
{
    int r = blockIdx.x, n = r & (SEQ-1);
    const float* ep = emb + (long long)ids[r]*DM;
    const float* pp = pos + (long long)n*DM;
    for (int d = threadIdx.x; d < DM; d += 256){
        float v = ep[d] + pp[d];
        X[(long long)r*DM+d] = v; H[(long long)r*DM+d] = v;
    }
}

// ---------------- scan layer: LN + z/a projections --------------------------
__global__ void __launch_bounds__(256)
lnproj_k(const float* __restrict__ H, const float* __restrict__ Win, const float* __restrict__ Wg,
         const float* __restrict__ gam, const float* __restrict__ bet,
         float* __restrict__ bufZ, float* __restrict__ bufA)
{
    __shared__ float sX[32][64];
    __shared__ float sW[64*128];
    const int c = blockIdx.x, r0 = blockIdx.y*32, tid = threadIdx.x;
    for (int i=tid;i<32*64;i+=256){
        int row=i>>6, d=i&63;
        sX[row][d] = H[(((long long)(r0+row))*CC+c)*DC+d];
    }
    __syncthreads();
    const int w = tid>>5, lane = tid&31;
    for (int row=w; row<32; row+=8){
        float x0=sX[row][lane], x1=sX[row][lane+32];
        float sm=x0+x1;
        #pragma unroll
        for (int o=16;o;o>>=1) sm += __shfl_xor_sync(0xffffffffu, sm, o);
        float mu = sm*(1.f/64.f);
        float d0=x0-mu, d1=x1-mu;
        float vs=d0*d0+d1*d1;
        #pragma unroll
        for (int o=16;o;o>>=1) vs += __shfl_xor_sync(0xffffffffu, vs, o);
        float inv = rsqrtf(vs*(1.f/64.f)+1e-5f);
        sX[row][lane]    = d0*inv*gam[lane]   +bet[lane];
        sX[row][lane+32] = d1*inv*gam[lane+32]+bet[lane+32];
    }
    __syncthreads();
    for (int i=tid;i<64*128/4;i+=256)
        reinterpret_cast<float4*>(sW)[i] = reinterpret_cast<const float4*>(Win + c*64*128)[i];
    __syncthreads();
    for (int qd=tid; qd<1024; qd+=256){
        int row=qd>>5, e0=(qd&31)<<2;
        float4 a=make_float4(0,0,0,0);
        #pragma unroll 8
        for (int d=0;d<64;d++){
            float xv=sX[row][d];
            float4 wv=*reinterpret_cast<const float4*>(&sW[d*128+e0]);
            a.x=fmaf(xv,wv.x,a.x); a.y=fmaf(xv,wv.y,a.y); a.z=fmaf(xv,wv.z,a.z); a.w=fmaf(xv,wv.w,a.w);
        }
        *reinterpret_cast<float4*>(&bufZ[(((long long)(r0+row))*CC+c)*EE+e0]) = a;
    }
    __syncthreads();
    for (int i=tid;i<64*128/4;i+=256)
        reinterpret_cast<float4*>(sW)[i] = reinterpret_cast<const float4*>(Wg + c*64*128)[i];
    __syncthreads();
    for (int qd=tid; qd<1024; qd+=256){
        int row=qd>>5, e0=(qd&31)<<2;
        float4 a=make_float4(0,0,0,0);
        #pragma unroll 8
        for (int d=0;d<64;d++){
            float xv=sX[row][d];
            float4 wv=*reinterpret_cast<const float4*>(&sW[d*128+e0]);
            a.x=fmaf(xv,wv.x,a.x); a.y=fmaf(xv,wv.y,a.y); a.z=fmaf(xv,wv.z,a.z); a.w=fmaf(xv,wv.w,a.w);
        }
        a.x=sigm(a.x); a.y=sigm(a.y); a.z=sigm(a.z); a.w=sigm(a.w);
        *reinterpret_cast<float4*>(&bufA[(((long long)(r0+row))*CC+c)*EE+e0]) = a;
    }
}

// ---------------- gated recurrence over time --------------------------------
__global__ void scan_k(float* __restrict__ Z, const float* __restrict__ A)
{
    int ch = blockIdx.x*256 + threadIdx.x;
    const int str = CC*EE;
    long long p = (long long)(ch>>11)*((long long)SEQ*str) + (ch & (str-1));
    float h = 0.f;
    for (int n=0;n<SEQ;n+=4){
        float z0=Z[p], z1=Z[p+str], z2=Z[p+2*str], z3=Z[p+3*str];
        float a0=A[p], a1=A[p+str], a2=A[p+2*str], a3=A[p+3*str];
        h = fmaf(a0, h-z0, z0); Z[p]=h;
        h = fmaf(a1, h-z1, z1); Z[p+str]=h;
        h = fmaf(a2, h-z2, z2); Z[p+2*str]=h;
        h = fmaf(a3, h-z3, z3); Z[p+3*str]=h;
        p += 4*str;
    }
}

// ---------------- scan output projection + residual -------------------------
__global__ void __launch_bounds__(256)
outproj_k(const float* __restrict__ hbuf, const float* __restrict__ Wout, float* __restrict__ H)
{
    __shared__ float sh[16][128];
    __shared__ float sW[128*64];
    const int c = blockIdx.x, r0 = blockIdx.y*16, tid = threadIdx.x;
    for (int i=tid;i<16*128/4;i+=256){
        int row=i>>5, e0=(i&31)<<2;
        *reinterpret_cast<float4*>(&sh[row][e0]) =
            *reinterpret_cast<const float4*>(&hbuf[(((long long)(r0+row))*CC+c)*EE+e0]);
    }
    for (int i=tid;i<128*64/4;i+=256)
        reinterpret_cast<float4*>(sW)[i] = reinterpret_cast<const float4*>(Wout + c*128*64)[i];
    __syncthreads();
    int row = tid>>4, d0 = (tid&15)<<2;
    float4 a=make_float4(0,0,0,0);
    #pragma unroll 8
    for (int e=0;e<128;e++){
        float hv=sh[row][e];
        float4 wv=*reinterpret_cast<const float4*>(&sW[e*64+d0]);
        a.x=fmaf(hv,wv.x,a.x); a.y=fmaf(hv,wv.y,a.y); a.z=fmaf(hv,wv.z,a.z); a.w=fmaf(hv,wv.w,a.w);
    }
    long long o = (((long long)(r0+row))*CC+c)*DC+d0;
    float4 h0 = *reinterpret_cast<const float4*>(&H[o]);
    a.x+=h0.x; a.y+=h0.y; a.z+=h0.z; a.w+=h0.w;
    *reinterpret_cast<float4*>(&H[o]) = a;
}

// ---------------- PCM -------------------------------------------------------
__global__ void __launch_bounds__(256)
pcm_k(float* __restrict__ H, const float* __restrict__ X, const float* __restrict__ Wpred,
      float* __restrict__ surp, float* __restrict__ auxp)
{
    __shared__ float sH[32][64];
    __shared__ float sW[64*64];
    __shared__ float sred[32];
    const int c = blockIdx.x, r0 = blockIdx.y*32, tid = threadIdx.x;
    for (int i=tid;i<32*64;i+=256){
        int row=i>>6, d=i&63;
        sH[row][d] = H[(((long long)(r0+row))*CC+c)*DC+d];
    }
    for (int i=tid;i<64*64/4;i+=256)
        reinterpret_cast<float4*>(sW)[i] = reinterpret_cast<const float4*>(Wpred + c*64*64)[i];
    __syncthreads();
    float auxa = 0.f;
    for (int qd=tid; qd<512; qd+=256){
        int row=qd>>4, d0=(qd&15)<<2;
        float4 a=make_float4(0,0,0,0);
        #pragma unroll 8
        for (int d=0;d<64;d++){
            float hv=sH[row][d];
            float4 wv=*reinterpret_cast<const float4*>(&sW[d*64+d0]);
            a.x=fmaf(hv,wv.x,a.x); a.y=fmaf(hv,wv.y,a.y); a.z=fmaf(hv,wv.z,a.z); a.w=fmaf(hv,wv.w,a.w);
        }
        long long gi = (((long long)(r0+row))*CC+c)*DC+d0;
        float4 xv = *reinterpret_cast<const float4*>(&X[gi]);
        float dx=a.x-xv.x, dy=a.y-xv.y, dz=a.z-xv.z, dw=a.w-xv.w;
        auxa += dx*dx+dy*dy+dz*dz+dw*dw;
        float4 sp = make_float4(fabsf(dx),fabsf(dy),fabsf(dz),fabsf(dw));
        *reinterpret_cast<float4*>(&surp[gi]) = sp;
        float4 hn;
        hn.x = sH[row][d0+0]*(1.f+tanhf(sp.x));
        hn.y = sH[row][d0+1]*(1.f+tanhf(sp.y));
        hn.z = sH[row][d0+2]*(1.f+tanhf(sp.z));
        hn.w = sH[row][d0+3]*(1.f+tanhf(sp.w));
        *reinterpret_cast<float4*>(&H[gi]) = hn;
    }
    float tot = blockSum256(auxa, sred);
    if (tid==0) auxp[blockIdx.y*CC + c] = tot;
}

// ---------------- seed & w_cand (float + packed wc) -------------------------
__global__ void __launch_bounds__(256)
seedw_k(const float* __restrict__ H, const float* __restrict__ Ws, const float* __restrict__ Ww,
        float* __restrict__ seed, float* __restrict__ wc, unsigned* __restrict__ wcp)
{
    __shared__ float sH[32][64];
    __shared__ float sWa[64*64];
    __shared__ float sWb[64*64];
    const int c = blockIdx.x, r0 = blockIdx.y*32, tid = threadIdx.x;
    for (int i=tid;i<32*64;i+=256){
        int row=i>>6, d=i&63;
        sH[row][d] = H[(((long long)(r0+row))*CC+c)*DC+d];
    }
    for (int i=tid;i<64*64/4;i+=256){
        reinterpret_cast<float4*>(sWa)[i] = reinterpret_cast<const float4*>(Ws + c*64*64)[i];
        reinterpret_cast<float4*>(sWb)[i] = reinterpret_cast<const float4*>(Ww + c*64*64)[i];
    }
    __syncthreads();
    for (int qd=tid; qd<512; qd+=256){
        int row=qd>>4, d0=(qd&15)<<2;
        float4 a=make_float4(0,0,0,0), b=make_float4(0,0,0,0);
        #pragma unroll 8
        for (int d=0;d<64;d++){
            float hv=sH[row][d];
            float4 wa=*reinterpret_cast<const float4*>(&sWa[d*64+d0]);
            float4 wb=*reinterpret_cast<const float4*>(&sWb[d*64+d0]);
            a.x=fmaf(hv,wa.x,a.x); a.y=fmaf(hv,wa.y,a.y); a.z=fmaf(hv,wa.z,a.z); a.w=fmaf(hv,wa.w,a.w);
            b.x=fmaf(hv,wb.x,b.x); b.y=fmaf(hv,wb.y,b.y); b.z=fmaf(hv,wb.z,b.z); b.w=fmaf(hv,wb.w,b.w);
        }
        long long gi = (((long long)(r0+row))*CC+c)*DC+d0;
        *reinterpret_cast<float4*>(&seed[gi]) = a;
        *reinterpret_cast<float4*>(&wc[gi]) = b;
        *reinterpret_cast<uint4*>(&wcp[gi]) = packhl4(b);
    }
}

// ---------------- per-row stats ---------------------------------------------
__global__ void __launch_bounds__(256)
rowstat_k(const float* __restrict__ surp, const float* __restrict__ wc,
          const float* __restrict__ Hf, const float* __restrict__ Wnv,
          const float* __restrict__ Wnb, float* __restrict__ smg,
          float* __restrict__ wiv, float* __restrict__ wnv)
{
    __shared__ float sred[32];
    const int r = blockIdx.x, tid = threadIdx.x;
    long long base = (long long)r*DM + tid*4;
    float4 sv = *reinterpret_cast<const float4*>(surp + base);
    float4 wv = *reinterpret_cast<const float4*>(wc + base);
    float4 hv = *reinterpret_cast<const float4*>(Hf + base);
    float s1 = sv.x+sv.y+sv.z+sv.w;
    float s2 = wv.x*wv.x+wv.y*wv.y+wv.z*wv.z+wv.w*wv.w;
    float t1 = blockSum256(s1, sred);
    if (tid==0) smg[r] = sigm(t1*(1.f/(float)DM));
    float t2 = blockSum256(s2, sred);
    if (tid==0) wiv[r] = 1.f/(sqrtf(t2)+1e-6f);
    float acc[NBK];
    #pragma unroll
    for (int b=0;b<NBK;b++) acc[b]=0.f;
    float hvv[4] = {hv.x,hv.y,hv.z,hv.w};
    #pragma unroll
    for (int j=0;j<4;j++){
        const float* wr = Wnv + (tid*4+j)*NBK;
        #pragma unroll
        for (int b=0;b<NBK;b++) acc[b] = fmaf(hvv[j], wr[b], acc[b]);
    }
    #pragma unroll
    for (int b=0;b<NBK;b++){
        float t = blockSum256(acc[b], sred);
        if (tid==0) wnv[r*NBK+b] = sigm(t + Wnb[b]);
    }
}

// ---------------- em_K inverse norms ----------------------------------------
__global__ void knorm_k(const float* __restrict__ emK, float* __restrict__ kiv)
{
    __shared__ float sred[32];
    const int row = blockIdx.x;
    float4 v = *reinterpret_cast<const float4*>(emK + (long long)row*DM + threadIdx.x*4);
    float s = v.x*v.x+v.y*v.y+v.z*v.z+v.w*v.w;
    float t = blockSum256(s, sred);
    if (threadIdx.x==0) kiv[row] = 1.f/(sqrtf(t)+1e-6f);
}

// ---------------- cumsum over time (in-place float) -------------------------
__global__ void cumsum_k(float* __restrict__ X)
{
    int ch = blockIdx.x*256 + threadIdx.x;
    long long p = (long long)(ch>>10)*((long long)SEQ*DM) + (ch & (DM-1));
    float h = 0.f;
    for (int n=0;n<SEQ;n+=4){
        float v0=X[p], v1=X[p+DM], v2=X[p+2*DM], v3=X[p+3*DM];
        h+=v0; X[p]=h; h+=v1; X[p+DM]=h; h+=v2; X[p+2*DM]=h; h+=v3; X[p+3*DM]=h;
        p += 4*DM;
    }
}

// ---------------- cumsum over time -> packed output -------------------------
__global__ void cumsum_pack_k(const float* __restrict__ X, unsigned* __restrict__ P)
{
    int ch = blockIdx.x*256 + threadIdx.x;
    long long p = (long long)(ch>>10)*((long long)SEQ*DM) + (ch & (DM-1));
    float h = 0.f;
    for (int n=0;n<SEQ;n+=4){
        h += X[p];        P[p]       = packhl(h);
        h += X[p+DM];     P[p+DM]    = packhl(h);
        h += X[p+2*DM];   P[p+2*DM]  = packhl(h);
        h += X[p+3*DM];   P[p+3*DM]  = packhl(h);
        p += 4*DM;
    }
}

// ---------------- pm sigmoid-sum epilogue -----------------------------------
__global__ void pmsum_k(const float* __restrict__ dpm, const float* __restrict__ pmst,
                        float* __restrict__ pms)
{
    const int r = blockIdx.x, s = r >> 10;
    for (int d = threadIdx.x; d < DM; d += 256){
        float acc = 0.f;
        #pragma unroll
        for (int b=0;b<NBK;b++)
            acc += sigm(pmst[((long long)s*NBK+b)*DM+d] + dpm[((long long)b*NR + r)*DM + d]);
        pms[(long long)r*DM+d] = acc;
    }
}

// ---------------- novelty -> summed write gate ------------------------------
__global__ void novel_k(const float* __restrict__ sim, const float* __restrict__ wnv,
                        const float* __restrict__ smg, const float* __restrict__ wiv,
                        const float* __restrict__ kiv, float* __restrict__ nvs)
{
    __shared__ float snov[NBK];
    const int r = blockIdx.x, s = r >> 10, n = r & (SEQ-1);
    const int b = threadIdx.x >> 5, lane = threadIdx.x & 31;
    const int z = s*NBK + b;
    const float* sp = sim + ((long long)z*SEQ + n)*MS;
    const float* kp = kiv + z*MS;
    float m = fmaxf(sp[lane]*kp[lane], sp[lane+32]*kp[lane+32]);
    #pragma unroll
    for (int o=16;o;o>>=1) m = fmaxf(m, __shfl_xor_sync(0xffffffffu, m, o));
    if (lane==0){
        float msim = m * wiv[r];
        snov[b] = wnv[r*NBK+b] * smg[r] * fmaxf(0.f, 1.f - msim);
    }
    __syncthreads();
    if (threadIdx.x==0){
        float t=0.f;
        #pragma unroll
        for (int i=0;i<NBK;i++) t += snov[i];
        nvs[r] = t;
    }
}

__global__ void cem_k(const float* __restrict__ nvs, const float* __restrict__ wc,
                      float* __restrict__ cem)
{
    const int r = blockIdx.x;
    float nv = nvs[r];
    long long base = (long long)r*DM + threadIdx.x*4;
    float4 v = *reinterpret_cast<const float4*>(wc + base);
    v.x*=nv; v.y*=nv; v.z*=nv; v.w*=nv;
    *reinterpret_cast<float4*>(cem + base) = v;
}

// ---------------- trail attention pieces ------------------------------------
__global__ void qinit_k(const float* __restrict__ seed, unsigned* __restrict__ qp)
{
    long long f = (long long)blockIdx.x*256 + threadIdx.x;
    const long long per = (long long)SEQ*DM/4;
    for (int it=0; it<4; it++, f += (long long)8192*256){
        long long z = f / per, rem = f - z*per;
        long long s = z >> 3;
        reinterpret_cast<uint4*>(qp)[f] =
            packhl4(reinterpret_cast<const float4*>(seed)[s*per + rem]);
    }
}

__global__ void softmax_k(const float* __restrict__ sim, unsigned* __restrict__ simp)
{
    const int row = blockIdx.x*8 + (threadIdx.x>>5);
    const int lane = threadIdx.x & 31;
    const float* p = sim + (long long)row*MS;
    unsigned* q = simp + (long long)row*MS;
    const float scale = 0.03125f;
    float a = p[lane]*scale, b = p[lane+32]*scale;
    float m = fmaxf(a,b);
    #pragma unroll
    for (int o=16;o;o>>=1) m = fmaxf(m, __shfl_xor_sync(0xffffffffu, m, o));
    float ea = expf(a-m), eb = expf(b-m);
    float s = ea+eb;
    #pragma unroll
    for (int o=16;o;o>>=1) s += __shfl_xor_sync(0xffffffffu, s, o);
    float inv = 1.f/s;
    q[lane] = packhl(ea*inv); q[lane+32] = packhl(eb*inv);
}

// ---------------- integrate reads -------------------------------------------
__global__ void integrate_k(const float* __restrict__ Hf, const float* __restrict__ pms,
                            const float* __restrict__ q, const float* __restrict__ cem,
                            float* __restrict__ out)
{
    const int r = blockIdx.x, s = r >> 10, n = r & (SEQ-1);
    long long base = (long long)r*DM + threadIdx.x*4;
    float4 hv = *reinterpret_cast<const float4*>(Hf + base);
    float4 pv = *reinterpret_cast<const float4*>(pms + base);
    float4 cv = *reinterpret_cast<const float4*>(cem + base);
    float4 a;
    a.x = hv.x*pv.x + cv.x; a.y = hv.y*pv.y + cv.y;
    a.z = hv.z*pv.z + cv.z; a.w = hv.w*pv.w + cv.w;
    #pragma unroll
    for (int b=0;b<NBK;b++){
        float4 qv = *reinterpret_cast<const float4*>(
            q + (((long long)(s*NBK+b))*SEQ + n)*DM + threadIdx.x*4);
        a.x += qv.x; a.y += qv.y; a.z += qv.z; a.w += qv.w;
    }
    *reinterpret_cast<float4*>(out + base) = a;
}

// ---------------- final LN -> packed lno ------------------------------------
__global__ void finalln_k(const float* __restrict__ X, const float* __restrict__ g,
                          const float* __restrict__ b, unsigned* __restrict__ O)
{
    __shared__ float sred[32];
    const int r = blockIdx.x, tid = threadIdx.x;
    long long base = (long long)r*DM + tid*4;
    float4 v = *reinterpret_cast<const float4*>(X + base);
    float s1 = v.x+v.y+v.z+v.w;
    float mu = blockSum256(s1, sred)*(1.f/(float)DM);
    float dx=v.x-mu, dy=v.y-mu, dz=v.z-mu, dw=v.w-mu;
    float s2 = dx*dx+dy*dy+dz*dz+dw*dw;
    float inv = rsqrtf(blockSum256(s2, sred)*(1.f/(float)DM) + 1e-5f);
    float4 gv = *reinterpret_cast<const float4*>(g + tid*4);
    float4 bv = *reinterpret_cast<const float4*>(b + tid*4);
    float4 o;
    o.x = dx*inv*gv.x+bv.x; o.y = dy*inv*gv.y+bv.y;
    o.z = dz*inv*gv.z+bv.z; o.w = dw*inv*gv.w+bv.w;
    *reinterpret_cast<uint4*>(O + base) = packhl4(o);
}

__global__ void auxfin_k(const float* __restrict__ auxp, float* __restrict__ out)
{
    __shared__ float sred[32];
    float a = 0.f;
    for (int i = threadIdx.x; i < 2048; i += 256) a += auxp[i];
    float t = blockSum256(a, sred);
    if (threadIdx.x==0) out[LOGN] = t * (0.1f/((float)NR*(float)DM));
}

// ---------------- host ------------------------------------------------------
extern "C" void kernel_launch(void* const* d_in, const int* in_sizes, int n_in,
                              void* d_out, int out_size)
{
    const int*   ids   = (const int*)  d_in[0];
    const float* emb   = (const float*)d_in[1];
    const float* pos   = (const float*)d_in[2];
    const float* s1Win = (const float*)d_in[3];
    const float* s1Wg  = (const float*)d_in[4];
    const float* s1Wo  = (const float*)d_in[5];
    const float* s1g   = (const float*)d_in[6];
    const float* s1b   = (const float*)d_in[7];
    const float* s3Win = (const float*)d_in[8];
    const float* s3Wg  = (const float*)d_in[9];
    const float* s3Wo  = (const float*)d_in[10];
    const float* s3g   = (const float*)d_in[11];
    const float* s3b   = (const float*)d_in[12];
    const float* Wseed = (const float*)d_in[13];
    const float* Ww    = (const float*)d_in[14];
    const float* Wpred = (const float*)d_in[15];
    const float* Wnv   = (const float*)d_in[16];
    const float* Wnb   = (const float*)d_in[17];
    const float* Wdel  = (const float*)d_in[18];
    const float* pmst  = (const float*)d_in[19];
    const float* emK   = (const float*)d_in[20];
    const float* emV   = (const float*)d_in[21];
    const float* lng   = (const float*)d_in[22];
    const float* lnb   = (const float*)d_in[23];
    float* out = (float*)d_out;

    float *X,*H,*bZ,*bA,*S,*seed,*wc,*pms,*dpm,*q,*sim;
    float *wnv,*smg,*nvs,*wiv,*kiv,*auxp;
    unsigned *pemb,*pwdel,*plno,*pS,*pwc,*pemK,*pemV,*pq,*psim;
    cudaGetSymbolAddress((void**)&X, g_X);
    cudaGetSymbolAddress((void**)&H, g_H);
    cudaGetSymbolAddress((void**)&bZ, g_bufZ);
    cudaGetSymbolAddress((void**)&bA, g_bufA);
    cudaGetSymbolAddress((void**)&S, g_surp);
    cudaGetSymbolAddress((void**)&seed, g_seed);
    cudaGetSymbolAddress((void**)&wc, g_wc);
    cudaGetSymbolAddress((void**)&pms, g_pms);
    cudaGetSymbolAddress((void**)&dpm, g_dpm);
    cudaGetSymbolAddress((void**)&q, g_q);
    cudaGetSymbolAddress((void**)&sim, g_sim);
    cudaGetSymbolAddress((void**)&wnv, g_wnv);
    cudaGetSymbolAddress((void**)&smg, g_smg);
    cudaGetSymbolAddress((void**)&nvs, g_nvs);
    cudaGetSymbolAddress((void**)&wiv, g_wiv);
    cudaGetSymbolAddress((void**)&kiv, g_kiv);
    cudaGetSymbolAddress((void**)&auxp, g_aux);
    cudaGetSymbolAddress((void**)&pemb, p_emb);
    cudaGetSymbolAddress((void**)&pwdel, p_wdel);
    cudaGetSymbolAddress((void**)&plno, p_lno);
    cudaGetSymbolAddress((void**)&pS, p_S);
    cudaGetSymbolAddress((void**)&pwc, p_wc);
    cudaGetSymbolAddress((void**)&pemK, p_emK);
    cudaGetSymbolAddress((void**)&pemV, p_emV);
    cudaGetSymbolAddress((void**)&pq, p_q);
    cudaGetSymbolAddress((void**)&psim, p_sim);

    const long long sND = (long long)SEQ*DM;
    const long long sMD = (long long)MS*DM;
    const long long sNM = (long long)SEQ*MS;

    // pack constants
    pack_k<<<2048,256>>>(emb, pemb, (long long)VOC*DM/4);
    pack_k<<<1024,256>>>(Wdel, pwdel, (long long)NBK*DM*DM/4);
    pack_k<<<256,256>>>(emK, pemK, (long long)BSZ*NBK*MS*DM/4);
    pack_k<<<256,256>>>(emV, pemV, (long long)BSZ*NBK*MS*DM/4);

    embed_k<<<NR,256>>>(ids, emb, pos, X, H);

    for (int l=0;l<2;l++){
        lnproj_k<<<dim3(CC,NR/32),256>>>(H, s1Win+l*CC*DC*EE, s1Wg+l*CC*DC*EE,
                                         s1g+l*DC, s1b+l*DC, bZ, bA);
        scan_k<<<32,256>>>(bZ, bA);
        outproj_k<<<dim3(CC,NR/16),256>>>(bZ, s1Wo+l*CC*EE*DC, H);
    }

    pcm_k<<<dim3(CC,NR/32),256>>>(H, X, Wpred, S, auxp);
    seedw_k<<<dim3(CC,NR/32),256>>>(H, Wseed, Ww, seed, wc, pwc);
    rowstat_k<<<NR,256>>>(S, wc, H, Wnv, Wnb, smg, wiv, wnv);
    knorm_k<<<BSZ*NBK*MS,256>>>(emK, kiv);

    // similarity: w_cand @ em_K^T per (s,b)
    hgemm_k<true><<<dim3(1,SEQ/128,BSZ*NBK),256>>>(pwc, pemK, sim, (unsigned*)0,
        SEQ, MS, DM, DM, DM, MS, sND, sMD, sNM, NBK, 1.f);
    novel_k<<<NR,256>>>(sim, wnv, smg, wiv, kiv, nvs);
    cem_k<<<NR,256>>>(nvs, wc, bZ);
    cumsum_k<<<16,256>>>(bZ);

    // procedural memory: packed cumsum(surp) then 8 batched GEMMs vs W_delta
    cumsum_pack_k<<<16,256>>>(S, pS);
    hgemm_k<false><<<dim3(DM/128,NR/128,NBK),256>>>(pS, pwdel, dpm, (unsigned*)0,
        NR, DM, DM, DM, DM, DM, 0, (long long)DM*DM, (long long)NR*DM, NBK, 1.f);
    pmsum_k<<<NR,256>>>(dpm, pmst, pms);

    // trail attention
    qinit_k<<<8192,256>>>(seed, pq);
    for (int t=0;t<4;t++){
        hgemm_k<true><<<dim3(1,SEQ/128,BSZ*NBK),256>>>(pq, pemK, sim, (unsigned*)0,
            SEQ, MS, DM, DM, DM, MS, sND, sMD, sNM, 1, 1.f);
        softmax_k<<<BSZ*NBK*SEQ/8,256>>>(sim, psim);
        hgemm_k<false><<<dim3(DM/128,SEQ/128,BSZ*NBK),256>>>(psim, pemV, q, pq,
            SEQ, DM, MS, MS, DM, DM, sNM, sMD, sND, 1, 1.f);
    }

    integrate_k<<<NR,256>>>(H, pms, q, bZ, X);

    for (int l=0;l<2;l++){
        lnproj_k<<<dim3(CC,NR/32),256>>>(X, s3Win+l*CC*DC*EE, s3Wg+l*CC*DC*EE,
                                         s3g+l*DC, s3b+l*DC, bZ, bA);
        scan_k<<<32,256>>>(bZ, bA);
        outproj_k<<<dim3(CC,NR/16),256>>>(bZ, s3Wo+l*CC*EE*DC, X);
    }

    finalln_k<<<NR,256>>>(X, lng, lnb, plno);

    // logits: lno [4096,1024] @ emb^T [1024,32000]
    hgemm_k<true><<<dim3(VOC/128,NR/128,1),256>>>(plno, pemb, out, (unsigned*)0,
        NR, VOC, DM, DM, DM, VOC, 0, 0, 0, 1, 1.f);

    if ((long long)out_size > LOGN)
        auxfin_k<<<1,256>>>(auxp, out);
}

// round 13
// speedup vs baseline: 1.6841x; 1.0143x over previous
#include <cuda_runtime.h>
#include <cuda_bf16.h>
#include <stdint.h>
#include <math.h>

#define BSZ 4
#define SEQ 1024
#define VOC 32000
#define DM 1024
#define CC 16
#define DC 64
#define NBK 8
#define MS 64
#define EE 128
#define NR (BSZ*SEQ)
#define LOGN ((long long)NR*VOC)

// ---------------- float scratch ----------------------------------------------
__device__ float g_X[NR*DM];
__device__ float g_H[NR*DM];
__device__ float g_bufZ[NR*CC*EE];
__device__ float g_bufA[NR*CC*EE];
__device__ float g_surp[NR*DM];
__device__ float g_seed[NR*DM];
__device__ float g_wc[NR*DM];
__device__ float g_pms[NR*DM];
__device__ float g_dpm[(long long)NBK*NR*DM];
__device__ float g_q[(long long)BSZ*NBK*SEQ*DM];
__device__ float g_sim[(long long)BSZ*NBK*SEQ*MS];
__device__ float g_wnv[NR*NBK];
__device__ float g_smg[NR];
__device__ float g_nvs[NR];
__device__ float g_wiv[NR];
__device__ float g_kiv[BSZ*NBK*MS];
__device__ float g_aux[2048];

// ---------------- packed (hi-bf16 | lo-bf16) operand buffers ------------------
__device__ unsigned p_emb[(long long)VOC*DM];
__device__ unsigned p_wdel[(long long)NBK*DM*DM];
__device__ unsigned p_lno[NR*DM];
__device__ unsigned p_S[NR*DM];
__device__ unsigned p_wc[NR*DM];
__device__ unsigned p_emK[BSZ*NBK*MS*DM];
__device__ unsigned p_emV[BSZ*NBK*MS*DM];
__device__ unsigned p_q[(long long)BSZ*NBK*SEQ*DM];
__device__ unsigned p_sim[(long long)BSZ*NBK*SEQ*MS];

__device__ __forceinline__ float sigm(float x){ return 1.f/(1.f+expf(-x)); }

__device__ __forceinline__ unsigned packhl(float x){
    __nv_bfloat16 h = __float2bfloat16(x);
    float hf = __bfloat162float(h);
    __nv_bfloat16 l = __float2bfloat16(x - hf);
    return (unsigned)__bfloat16_as_ushort(h) | ((unsigned)__bfloat16_as_ushort(l) << 16);
}
__device__ __forceinline__ uint4 packhl4(float4 v){
    uint4 o; o.x=packhl(v.x); o.y=packhl(v.y); o.z=packhl(v.z); o.w=packhl(v.w); return o;
}

__device__ __forceinline__ float blockSum256(float v, float* sred){
    __syncthreads();
    int lane = threadIdx.x & 31, w = threadIdx.x >> 5;
    #pragma unroll
    for (int o=16;o;o>>=1) v += __shfl_xor_sync(0xffffffffu, v, o);
    if (lane==0) sred[w]=v;
    __syncthreads();
    float t = (threadIdx.x<8)? sred[threadIdx.x] : 0.f;
    if (w==0){
        #pragma unroll
        for (int o=4;o;o>>=1) t += __shfl_xor_sync(0xffffffffu, t, o);
        if (lane==0) sred[0]=t;
    }
    __syncthreads();
    return sred[0];
}

// ---------------- generic pack kernel ----------------------------------------
__global__ void pack_k(const float* __restrict__ in, unsigned* __restrict__ out, long long n4)
{
    long long i = (long long)blockIdx.x*256 + threadIdx.x;
    long long str = (long long)gridDim.x*256;
    for (; i < n4; i += str)
        reinterpret_cast<uint4*>(out)[i] = packhl4(reinterpret_cast<const float4*>(in)[i]);
}

// ---------------- tensor-core GEMM on pre-packed operands --------------------
__device__ __forceinline__ unsigned s2u(const void* p){
    unsigned a; asm("{ .reg .u64 t; cvta.to.shared.u64 t, %1; cvt.u32.u64 %0, t; }" : "=r"(a) : "l"(p));
    return a;
}
__device__ __forceinline__ void mma16816(float* c, const unsigned* a, unsigned b0, unsigned b1){
    asm volatile("mma.sync.aligned.m16n8k16.row.col.f32.bf16.bf16.f32 "
        "{%0,%1,%2,%3}, {%4,%5,%6,%7}, {%8,%9}, {%0,%1,%2,%3};"
        : "+f"(c[0]), "+f"(c[1]), "+f"(c[2]), "+f"(c[3])
        : "r"(a[0]), "r"(a[1]), "r"(a[2]), "r"(a[3]), "r"(b0), "r"(b1));
}
__device__ __forceinline__ void ldsm4(unsigned& r0, unsigned& r1, unsigned& r2, unsigned& r3, unsigned addr){
    asm volatile("ldmatrix.sync.aligned.m8n8.x4.shared.b16 {%0,%1,%2,%3}, [%4];"
        : "=r"(r0), "=r"(r1), "=r"(r2), "=r"(r3) : "r"(addr));
}
__device__ __forceinline__ void cpa16(unsigned dst, const void* src){
    asm volatile("cp.async.cg.shared.global [%0], [%1], 16;" :: "r"(dst), "l"(src));
}
__device__ __forceinline__ void cpa16z(unsigned dst, const void* src, int szbytes){
    asm volatile("cp.async.cg.shared.global [%0], [%1], 16, %2;" :: "r"(dst), "l"(src), "r"(szbytes));
}
#define CPA_COMMIT() asm volatile("cp.async.commit_group;" ::: "memory")
#define CPA_WAIT1()  asm volatile("cp.async.wait_group 1;" ::: "memory")

// smem layout: 3 stages; per stage: A tile rows[128]x20 u32, then B tile same.
// words/stage = 5120; total = 15360 u32 = 61440 B (dynamic).
template<bool TB>
__global__ void __launch_bounds__(256,2)
hgemm_k(const unsigned* __restrict__ Ag, const unsigned* __restrict__ Bg,
        float* __restrict__ Cg, unsigned* __restrict__ Cpg,
        int M, int Ncols, int K, int lda, int ldb, int ldc,
        long long sA, long long sB, long long sC, int zdivA, float alpha)
{
    extern __shared__ unsigned smem[];
    const int z = blockIdx.z;
    const unsigned* A = Ag + (long long)(z/zdivA)*sA;
    const unsigned* B = Bg + (long long)z*sB;
    float* C = Cg + (long long)z*sC;
    unsigned* Cp = Cpg ? (Cpg + (long long)z*sC) : (unsigned*)0;
    const int m0 = blockIdx.y*128, n0 = blockIdx.x*128;
    const int tid = threadIdx.x;
    const int wid = tid>>5, lane = tid&31;
    const int wm = (wid&1)*64, wn = (wid>>1)*32;
    const int r = lane>>2, cp = lane&3;
    const int arow = tid>>1, ahalf = tid&1;      // row-staging map (A and TB-B)
    const int bk = tid>>4, bn = (tid&15)*8;      // NN-B staging map

    const unsigned sb = s2u(smem);
    const int lrow = ((lane>>3)&1)*8 + (lane&7);
    const int lcol = (lane>>4)*4;
    unsigned aFB[4], bFB[2];
    #pragma unroll
    for (int i=0;i<4;i++) aFB[i] = sb + ((wm + i*16 + lrow)*20 + lcol)*4;
    #pragma unroll
    for (int jp=0;jp<2;jp++) bFB[jp] = sb + (2560 + (wn + jp*16 + lrow)*20 + lcol)*4;

    float acc[16][4];
    #pragma unroll
    for (int i=0;i<16;i++){ acc[i][0]=0.f; acc[i][1]=0.f; acc[i][2]=0.f; acc[i][3]=0.f; }

    const int nk = K >> 4;

    auto loadStage = [&](int kb, int s){
        unsigned aDst = sb + (unsigned)(s*5120 + arow*20 + ahalf*8)*4;
        const unsigned* ap = A + (long long)(m0+arow)*lda + kb + ahalf*8;
        cpa16(aDst, ap); cpa16(aDst+16, ap+4);
        if (TB){
            int nc = n0 + arow;
            int ok = (nc < Ncols) ? 16 : 0;
            const unsigned* bp = (nc < Ncols) ? (B + (long long)nc*ldb + kb + ahalf*8) : ap;
            unsigned bDst = sb + (unsigned)(s*5120 + 2560 + arow*20 + ahalf*8)*4;
            cpa16z(bDst, bp, ok); cpa16z(bDst+16, bp+4, ok);
        } else {
            unsigned* base = smem + s*5120 + 2560;
            const unsigned* p = B + (long long)(kb+bk)*ldb + n0 + bn;
            uint4 v0 = *reinterpret_cast<const uint4*>(p);
            uint4 v1 = *reinterpret_cast<const uint4*>(p+4);
            base[(bn+0)*20+bk]=v0.x; base[(bn+1)*20+bk]=v0.y;
            base[(bn+2)*20+bk]=v0.z; base[(bn+3)*20+bk]=v0.w;
            base[(bn+4)*20+bk]=v1.x; base[(bn+5)*20+bk]=v1.y;
            base[(bn+6)*20+bk]=v1.z; base[(bn+7)*20+bk]=v1.w;
        }
    };

    loadStage(0, 0); CPA_COMMIT();
    if (nk > 1) loadStage(16, 1);
    CPA_COMMIT();

    for (int t=0; t<nk; t++){
        const int s = t % 3;
        CPA_WAIT1();
        __syncthreads();
        const unsigned sOff = (unsigned)s*20480u;
        #pragma unroll
        for (int vk=0; vk<2; vk++){
            unsigned a[4][4];
            #pragma unroll
            for (int i=0;i<4;i++)
                ldsm4(a[i][0], a[i][1], a[i][2], a[i][3], aFB[i] + sOff + vk*32);
            unsigned w0[4], w1[4];
            #pragma unroll
            for (int jp=0;jp<2;jp++)
                ldsm4(w0[2*jp], w0[2*jp+1], w1[2*jp], w1[2*jp+1], bFB[jp] + sOff + vk*32);
            #pragma unroll
            for (int i=0;i<4;i++)
                #pragma unroll
                for (int j=0;j<4;j++){
                    mma16816(acc[i*4+j], a[i],
                             __byte_perm(w0[j], 0, 0x1010), __byte_perm(w1[j], 0, 0x1010));
                    mma16816(acc[i*4+j], a[i], w0[j]>>16, w1[j]>>16);
                }
        }
        if (t+2 < nk) loadStage((t+2)<<4, (t+2)%3);
        CPA_COMMIT();
    }
    #pragma unroll
    for (int i=0;i<4;i++){
        #pragma unroll
        for (int j=0;j<4;j++){
            const float* c = acc[i*4+j];
            int row = m0 + wm + i*16 + r;
            int col = n0 + wn + j*8 + 2*cp;
            if (col < Ncols){
                float v0 = alpha*c[0], v1 = alpha*c[1];
                float v2 = alpha*c[2], v3 = alpha*c[3];
                *reinterpret_cast<float2*>(C + (long long)row*ldc + col) = make_float2(v0,v1);
                *reinterpret_cast<float2*>(C + (long long)(row+8)*ldc + col) = make_float2(v2,v3);
                if (Cp){
                    Cp[(long long)row*ldc + col]   = packhl(v0);
                    Cp[(long long)row*ldc + col+1] = packhl(v1);
                    Cp[(long long)(row+8)*ldc + col]   = packhl(v2);
                    Cp[(long long)(row+8)*ldc + col+1] = packhl(v3);
                }
            }
        }
    }
}

// ---------------- embedding -------------------------------------------------
__global__ void embed_k(const int* __restrict__ ids, const float* __restrict__ emb,
                        const float* __restrict__ pos, float* __restrict__ X, float* __restrict__ H)
{
    int r = blockIdx.x, n = r & (SEQ-1);
    const float* ep = emb + (long long)ids[r]*DM;
    const float* pp = pos + (long long)n*DM;
    for (int d = threadIdx.x; d < DM; d += 256){
        float v = ep[d] + pp[d];
        X[(long long)r*DM+d] = v; H[(long long)r*DM+d] = v;
    }
}

// ---------------- scan layer: LN + z/a projections --------------------------
__global__ void __launch_bounds__(256)
lnproj_k(const float* __restrict__ H, const float* __restrict__ Win, const float* __restrict__ Wg,
         const float* __restrict__ gam, const float* __restrict__ bet,
         float* __restrict__ bufZ, float* __restrict__ bufA)
{
    __shared__ float sX[32][64];
    __shared__ float sW[64*128];
    const int c = blockIdx.x, r0 = blockIdx.y*32, tid = threadIdx.x;
    for (int i=tid;i<32*64;i+=256){
        int row=i>>6, d=i&63;
        sX[row][d] = H[(((long long)(r0+row))*CC+c)*DC+d];
    }
    __syncthreads();
    const int w = tid>>5, lane = tid&31;
    for (int row=w; row<32; row+=8){
        float x0=sX[row][lane], x1=sX[row][lane+32];
        float sm=x0+x1;
        #pragma unroll
        for (int o=16;o;o>>=1) sm += __shfl_xor_sync(0xffffffffu, sm, o);
        float mu = sm*(1.f/64.f);
        float d0=x0-mu, d1=x1-mu;
        float vs=d0*d0+d1*d1;
        #pragma unroll
        for (int o=16;o;o>>=1) vs += __shfl_xor_sync(0xffffffffu, vs, o);
        float inv = rsqrtf(vs*(1.f/64.f)+1e-5f);
        sX[row][lane]    = d0*inv*gam[lane]   +bet[lane];
        sX[row][lane+32] = d1*inv*gam[lane+32]+bet[lane+32];
    }
    __syncthreads();
    for (int i=tid;i<64*128/4;i+=256)
        reinterpret_cast<float4*>(sW)[i] = reinterpret_cast<const float4*>(Win + c*64*128)[i];
    __syncthreads();
    for (int qd=tid; qd<1024; qd+=256){
        int row=qd>>5, e0=(qd&31)<<2;
        float4 a=make_float4(0,0,0,0);
        #pragma unroll 8
        for (int d=0;d<64;d++){
            float xv=sX[row][d];
            float4 wv=*reinterpret_cast<const float4*>(&sW[d*128+e0]);
            a.x=fmaf(xv,wv.x,a.x); a.y=fmaf(xv,wv.y,a.y); a.z=fmaf(xv,wv.z,a.z); a.w=fmaf(xv,wv.w,a.w);
        }
        *reinterpret_cast<float4*>(&bufZ[(((long long)(r0+row))*CC+c)*EE+e0]) = a;
    }
    __syncthreads();
    for (int i=tid;i<64*128/4;i+=256)
        reinterpret_cast<float4*>(sW)[i] = reinterpret_cast<const float4*>(Wg + c*64*128)[i];
    __syncthreads();
    for (int qd=tid; qd<1024; qd+=256){
        int row=qd>>5, e0=(qd&31)<<2;
        float4 a=make_float4(0,0,0,0);
        #pragma unroll 8
        for (int d=0;d<64;d++){
            float xv=sX[row][d];
            float4 wv=*reinterpret_cast<const float4*>(&sW[d*128+e0]);
            a.x=fmaf(xv,wv.x,a.x); a.y=fmaf(xv,wv.y,a.y); a.z=fmaf(xv,wv.z,a.z); a.w=fmaf(xv,wv.w,a.w);
        }
        a.x=sigm(a.x); a.y=sigm(a.y); a.z=sigm(a.z); a.w=sigm(a.w);
        *reinterpret_cast<float4*>(&bufA[(((long long)(r0+row))*CC+c)*EE+e0]) = a;
    }
}

// ---------------- gated recurrence over time --------------------------------
__global__ void scan_k(float* __restrict__ Z, const float* __restrict__ A)
{
    int ch = blockIdx.x*256 + threadIdx.x;
    const int str = CC*EE;
    long long p = (long long)(ch>>11)*((long long)SEQ*str) + (ch & (str-1));
    float h = 0.f;
    for (int n=0;n<SEQ;n+=4){
        float z0=Z[p], z1=Z[p+str], z2=Z[p+2*str], z3=Z[p+3*str];
        float a0=A[p], a1=A[p+str], a2=A[p+2*str], a3=A[p+3*str];
        h = fmaf(a0, h-z0, z0); Z[p]=h;
        h = fmaf(a1, h-z1, z1); Z[p+str]=h;
        h = fmaf(a2, h-z2, z2); Z[p+2*str]=h;
        h = fmaf(a3, h-z3, z3); Z[p+3*str]=h;
        p += 4*str;
    }
}

// ---------------- scan output projection + residual -------------------------
__global__ void __launch_bounds__(256)
outproj_k(const float* __restrict__ hbuf, const float* __restrict__ Wout, float* __restrict__ H)
{
    __shared__ float sh[16][128];
    __shared__ float sW[128*64];
    const int c = blockIdx.x, r0 = blockIdx.y*16, tid = threadIdx.x;
    for (int i=tid;i<16*128/4;i+=256){
        int row=i>>5, e0=(i&31)<<2;
        *reinterpret_cast<float4*>(&sh[row][e0]) =
            *reinterpret_cast<const float4*>(&hbuf[(((long long)(r0+row))*CC+c)*EE+e0]);
    }
    for (int i=tid;i<128*64/4;i+=256)
        reinterpret_cast<float4*>(sW)[i] = reinterpret_cast<const float4*>(Wout + c*128*64)[i];
    __syncthreads();
    int row = tid>>4, d0 = (tid&15)<<2;
    float4 a=make_float4(0,0,0,0);
    #pragma unroll 8
    for (int e=0;e<128;e++){
        float hv=sh[row][e];
        float4 wv=*reinterpret_cast<const float4*>(&sW[e*64+d0]);
        a.x=fmaf(hv,wv.x,a.x); a.y=fmaf(hv,wv.y,a.y); a.z=fmaf(hv,wv.z,a.z); a.w=fmaf(hv,wv.w,a.w);
    }
    long long o = (((long long)(r0+row))*CC+c)*DC+d0;
    float4 h0 = *reinterpret_cast<const float4*>(&H[o]);
    a.x+=h0.x; a.y+=h0.y; a.z+=h0.z; a.w+=h0.w;
    *reinterpret_cast<float4*>(&H[o]) = a;
}

// ---------------- PCM -------------------------------------------------------
__global__ void __launch_bounds__(256)
pcm_k(float* __restrict__ H, const float* __restrict__ X, const float* __restrict__ Wpred,
      float* __restrict__ surp, float* __restrict__ auxp)
{
    __shared__ float sH[32][64];
    __shared__ float sW[64*64];
    __shared__ float sred[32];
    const int c = blockIdx.x, r0 = blockIdx.y*32, tid = threadIdx.x;
    for (int i=tid;i<32*64;i+=256){
        int row=i>>6, d=i&63;
        sH[row][d] = H[(((long long)(r0+row))*CC+c)*DC+d];
    }
    for (int i=tid;i<64*64/4;i+=256)
        reinterpret_cast<float4*>(sW)[i] = reinterpret_cast<const float4*>(Wpred + c*64*64)[i];
    __syncthreads();
    float auxa = 0.f;
    for (int qd=tid; qd<512; qd+=256){
        int row=qd>>4, d0=(qd&15)<<2;
        float4 a=make_float4(0,0,0,0);
        #pragma unroll 8
        for (int d=0;d<64;d++){
            float hv=sH[row][d];
            float4 wv=*reinterpret_cast<const float4*>(&sW[d*64+d0]);
            a.x=fmaf(hv,wv.x,a.x); a.y=fmaf(hv,wv.y,a.y); a.z=fmaf(hv,wv.z,a.z); a.w=fmaf(hv,wv.w,a.w);
        }
        long long gi = (((long long)(r0+row))*CC+c)*DC+d0;
        float4 xv = *reinterpret_cast<const float4*>(&X[gi]);
        float dx=a.x-xv.x, dy=a.y-xv.y, dz=a.z-xv.z, dw=a.w-xv.w;
        auxa += dx*dx+dy*dy+dz*dz+dw*dw;
        float4 sp = make_float4(fabsf(dx),fabsf(dy),fabsf(dz),fabsf(dw));
        *reinterpret_cast<float4*>(&surp[gi]) = sp;
        float4 hn;
        hn.x = sH[row][d0+0]*(1.f+tanhf(sp.x));
        hn.y = sH[row][d0+1]*(1.f+tanhf(sp.y));
        hn.z = sH[row][d0+2]*(1.f+tanhf(sp.z));
        hn.w = sH[row][d0+3]*(1.f+tanhf(sp.w));
        *reinterpret_cast<float4*>(&H[gi]) = hn;
    }
    float tot = blockSum256(auxa, sred);
    if (tid==0) auxp[blockIdx.y*CC + c] = tot;
}

// ---------------- seed & w_cand (float + packed wc) -------------------------
__global__ void __launch_bounds__(256)
seedw_k(const float* __restrict__ H, const float* __restrict__ Ws, const float* __restrict__ Ww,
        float* __restrict__ seed, float* __restrict__ wc, unsigned* __restrict__ wcp)
{
    __shared__ float sH[32][64];
    __shared__ float sWa[64*64];
    __shared__ float sWb[64*64];
    const int c = blockIdx.x, r0 = blockIdx.y*32, tid = threadIdx.x;
    for (int i=tid;i<32*64;i+=256){
        int row=i>>6, d=i&63;
        sH[row][d] = H[(((long long)(r0+row))*CC+c)*DC+d];
    }
    for (int i=tid;i<64*64/4;i+=256){
        reinterpret_cast<float4*>(sWa)[i] = reinterpret_cast<const float4*>(Ws + c*64*64)[i];
        reinterpret_cast<float4*>(sWb)[i] = reinterpret_cast<const float4*>(Ww + c*64*64)[i];
    }
    __syncthreads();
    for (int qd=tid; qd<512; qd+=256){
        int row=qd>>4, d0=(qd&15)<<2;
        float4 a=make_float4(0,0,0,0), b=make_float4(0,0,0,0);
        #pragma unroll 8
        for (int d=0;d<64;d++){
            float hv=sH[row][d];
            float4 wa=*reinterpret_cast<const float4*>(&sWa[d*64+d0]);
            float4 wb=*reinterpret_cast<const float4*>(&sWb[d*64+d0]);
            a.x=fmaf(hv,wa.x,a.x); a.y=fmaf(hv,wa.y,a.y); a.z=fmaf(hv,wa.z,a.z); a.w=fmaf(hv,wa.w,a.w);
            b.x=fmaf(hv,wb.x,b.x); b.y=fmaf(hv,wb.y,b.y); b.z=fmaf(hv,wb.z,b.z); b.w=fmaf(hv,wb.w,b.w);
        }
        long long gi = (((long long)(r0+row))*CC+c)*DC+d0;
        *reinterpret_cast<float4*>(&seed[gi]) = a;
        *reinterpret_cast<float4*>(&wc[gi]) = b;
        *reinterpret_cast<uint4*>(&wcp[gi]) = packhl4(b);
    }
}

// ---------------- per-row stats ---------------------------------------------
__global__ void __launch_bounds__(256)
rowstat_k(const float* __restrict__ surp, const float* __restrict__ wc,
          const float* __restrict__ Hf, const float* __restrict__ Wnv,
          const float* __restrict__ Wnb, float* __restrict__ smg,
          float* __restrict__ wiv, float* __restrict__ wnv)
{
    __shared__ float sred[32];
    const int r = blockIdx.x, tid = threadIdx.x;
    long long base = (long long)r*DM + tid*4;
    float4 sv = *reinterpret_cast<const float4*>(surp + base);
    float4 wv = *reinterpret_cast<const float4*>(wc + base);
    float4 hv = *reinterpret_cast<const float4*>(Hf + base);
    float s1 = sv.x+sv.y+sv.z+sv.w;
    float s2 = wv.x*wv.x+wv.y*wv.y+wv.z*wv.z+wv.w*wv.w;
    float t1 = blockSum256(s1, sred);
    if (tid==0) smg[r] = sigm(t1*(1.f/(float)DM));
    float t2 = blockSum256(s2, sred);
    if (tid==0) wiv[r] = 1.f/(sqrtf(t2)+1e-6f);
    float acc[NBK];
    #pragma unroll
    for (int b=0;b<NBK;b++) acc[b]=0.f;
    float hvv[4] = {hv.x,hv.y,hv.z,hv.w};
    #pragma unroll
    for (int j=0;j<4;j++){
        const float* wr = Wnv + (tid*4+j)*NBK;
        #pragma unroll
        for (int b=0;b<NBK;b++) acc[b] = fmaf(hvv[j], wr[b], acc[b]);
    }
    #pragma unroll
    for (int b=0;b<NBK;b++){
        float t = blockSum256(acc[b], sred);
        if (tid==0) wnv[r*NBK+b] = sigm(t + Wnb[b]);
    }
}

// ---------------- em_K inverse norms ----------------------------------------
__global__ void knorm_k(const float* __restrict__ emK, float* __restrict__ kiv)
{
    __shared__ float sred[32];
    const int row = blockIdx.x;
    float4 v = *reinterpret_cast<const float4*>(emK + (long long)row*DM + threadIdx.x*4);
    float s = v.x*v.x+v.y*v.y+v.z*v.z+v.w*v.w;
    float t = blockSum256(s, sred);
    if (threadIdx.x==0) kiv[row] = 1.f/(sqrtf(t)+1e-6f);
}

// ---------------- cumsum over time (in-place float) -------------------------
__global__ void cumsum_k(float* __restrict__ X)
{
    int ch = blockIdx.x*256 + threadIdx.x;
    long long p = (long long)(ch>>10)*((long long)SEQ*DM) + (ch & (DM-1));
    float h = 0.f;
    for (int n=0;n<SEQ;n+=4){
        float v0=X[p], v1=X[p+DM], v2=X[p+2*DM], v3=X[p+3*DM];
        h+=v0; X[p]=h; h+=v1; X[p+DM]=h; h+=v2; X[p+2*DM]=h; h+=v3; X[p+3*DM]=h;
        p += 4*DM;
    }
}

// ---------------- cumsum over time -> packed output -------------------------
__global__ void cumsum_pack_k(const float* __restrict__ X, unsigned* __restrict__ P)
{
    int ch = blockIdx.x*256 + threadIdx.x;
    long long p = (long long)(ch>>10)*((long long)SEQ*DM) + (ch & (DM-1));
    float h = 0.f;
    for (int n=0;n<SEQ;n+=4){
        h += X[p];        P[p]       = packhl(h);
        h += X[p+DM];     P[p+DM]    = packhl(h);
        h += X[p+2*DM];   P[p+2*DM]  = packhl(h);
        h += X[p+3*DM];   P[p+3*DM]  = packhl(h);
        p += 4*DM;
    }
}

// ---------------- pm sigmoid-sum epilogue -----------------------------------
__global__ void pmsum_k(const float* __restrict__ dpm, const float* __restrict__ pmst,
                        float* __restrict__ pms)
{
    const int r = blockIdx.x, s = r >> 10;
    for (int d = threadIdx.x; d < DM; d += 256){
        float acc = 0.f;
        #pragma unroll
        for (int b=0;b<NBK;b++)
            acc += sigm(pmst[((long long)s*NBK+b)*DM+d] + dpm[((long long)b*NR + r)*DM + d]);
        pms[(long long)r*DM+d] = acc;
    }
}

// ---------------- novelty -> summed write gate ------------------------------
__global__ void novel_k(const float* __restrict__ sim, const float* __restrict__ wnv,
                        const float* __restrict__ smg, const float* __restrict__ wiv,
                        const float* __restrict__ kiv, float* __restrict__ nvs)
{
    __shared__ float snov[NBK];
    const int r = blockIdx.x, s = r >> 10, n = r & (SEQ-1);
    const int b = threadIdx.x >> 5, lane = threadIdx.x & 31;
    const int z = s*NBK + b;
    const float* sp = sim + ((long long)z*SEQ + n)*MS;
    const float* kp = kiv + z*MS;
    float m = fmaxf(sp[lane]*kp[lane], sp[lane+32]*kp[lane+32]);
    #pragma unroll
    for (int o=16;o;o>>=1) m = fmaxf(m, __shfl_xor_sync(0xffffffffu, m, o));
    if (lane==0){
        float msim = m * wiv[r];
        snov[b] = wnv[r*NBK+b] * smg[r] * fmaxf(0.f, 1.f - msim);
    }
    __syncthreads();
    if (threadIdx.x==0){
        float t=0.f;
        #pragma unroll
        for (int i=0;i<NBK;i++) t += snov[i];
        nvs[r] = t;
    }
}

__global__ void cem_k(const float* __restrict__ nvs, const float* __restrict__ wc,
                      float* __restrict__ cem)
{
    const int r = blockIdx.x;
    float nv = nvs[r];
    long long base = (long long)r*DM + threadIdx.x*4;
    float4 v = *reinterpret_cast<const float4*>(wc + base);
    v.x*=nv; v.y*=nv; v.z*=nv; v.w*=nv;
    *reinterpret_cast<float4*>(cem + base) = v;
}

// ---------------- trail attention pieces ------------------------------------
__global__ void qinit_k(const float* __restrict__ seed, unsigned* __restrict__ qp)
{
    long long f = (long long)blockIdx.x*256 + threadIdx.x;
    const long long per = (long long)SEQ*DM/4;
    for (int it=0; it<4; it++, f += (long long)8192*256){
        long long z = f / per, rem = f - z*per;
        long long s = z >> 3;
        reinterpret_cast<uint4*>(qp)[f] =
            packhl4(reinterpret_cast<const float4*>(seed)[s*per + rem]);
    }
}

__global__ void softmax_k(const float* __restrict__ sim, unsigned* __restrict__ simp)
{
    const int row = blockIdx.x*8 + (threadIdx.x>>5);
    const int lane = threadIdx.x & 31;
    const float* p = sim + (long long)row*MS;
    unsigned* q = simp + (long long)row*MS;
    const float scale = 0.03125f;
    float a = p[lane]*scale, b = p[lane+32]*scale;
    float m = fmaxf(a,b);
    #pragma unroll
    for (int o=16;o;o>>=1) m = fmaxf(m, __shfl_xor_sync(0xffffffffu, m, o));
    float ea = expf(a-m), eb = expf(b-m);
    float s = ea+eb;
    #pragma unroll
    for (int o=16;o;o>>=1) s += __shfl_xor_sync(0xffffffffu, s, o);
    float inv = 1.f/s;
    q[lane] = packhl(ea*inv); q[lane+32] = packhl(eb*inv);
}

// ---------------- integrate reads -------------------------------------------
__global__ void integrate_k(const float* __restrict__ Hf, const float* __restrict__ pms,
                            const float* __restrict__ q, const float* __restrict__ cem,
                            float* __restrict__ out)
{
    const int r = blockIdx.x, s = r >> 10, n = r & (SEQ-1);
    long long base = (long long)r*DM + threadIdx.x*4;
    float4 hv = *reinterpret_cast<const float4*>(Hf + base);
    float4 pv = *reinterpret_cast<const float4*>(pms + base);
    float4 cv = *reinterpret_cast<const float4*>(cem + base);
    float4 a;
    a.x = hv.x*pv.x + cv.x; a.y = hv.y*pv.y + cv.y;
    a.z = hv.z*pv.z + cv.z; a.w = hv.w*pv.w + cv.w;
    #pragma unroll
    for (int b=0;b<NBK;b++){
        float4 qv = *reinterpret_cast<const float4*>(
            q + (((long long)(s*NBK+b))*SEQ + n)*DM + threadIdx.x*4);
        a.x += qv.x; a.y += qv.y; a.z += qv.z; a.w += qv.w;
    }
    *reinterpret_cast<float4*>(out + base) = a;
}

// ---------------- final LN -> packed lno ------------------------------------
__global__ void finalln_k(const float* __restrict__ X, const float* __restrict__ g,
                          const float* __restrict__ b, unsigned* __restrict__ O)
{
    __shared__ float sred[32];
    const int r = blockIdx.x, tid = threadIdx.x;
    long long base = (long long)r*DM + tid*4;
    float4 v = *reinterpret_cast<const float4*>(X + base);
    float s1 = v.x+v.y+v.z+v.w;
    float mu = blockSum256(s1, sred)*(1.f/(float)DM);
    float dx=v.x-mu, dy=v.y-mu, dz=v.z-mu, dw=v.w-mu;
    float s2 = dx*dx+dy*dy+dz*dz+dw*dw;
    float inv = rsqrtf(blockSum256(s2, sred)*(1.f/(float)DM) + 1e-5f);
    float4 gv = *reinterpret_cast<const float4*>(g + tid*4);
    float4 bv = *reinterpret_cast<const float4*>(b + tid*4);
    float4 o;
    o.x = dx*inv*gv.x+bv.x; o.y = dy*inv*gv.y+bv.y;
    o.z = dz*inv*gv.z+bv.z; o.w = dw*inv*gv.w+bv.w;
    *reinterpret_cast<uint4*>(O + base) = packhl4(o);
}

__global__ void auxfin_k(const float* __restrict__ auxp, float* __restrict__ out)
{
    __shared__ float sred[32];
    float a = 0.f;
    for (int i = threadIdx.x; i < 2048; i += 256) a += auxp[i];
    float t = blockSum256(a, sred);
    if (threadIdx.x==0) out[LOGN] = t * (0.1f/((float)NR*(float)DM));
}

// ---------------- host ------------------------------------------------------
extern "C" void kernel_launch(void* const* d_in, const int* in_sizes, int n_in,
                              void* d_out, int out_size)
{
    const int*   ids   = (const int*)  d_in[0];
    const float* emb   = (const float*)d_in[1];
    const float* pos   = (const float*)d_in[2];
    const float* s1Win = (const float*)d_in[3];
    const float* s1Wg  = (const float*)d_in[4];
    const float* s1Wo  = (const float*)d_in[5];
    const float* s1g   = (const float*)d_in[6];
    const float* s1b   = (const float*)d_in[7];
    const float* s3Win = (const float*)d_in[8];
    const float* s3Wg  = (const float*)d_in[9];
    const float* s3Wo  = (const float*)d_in[10];
    const float* s3g   = (const float*)d_in[11];
    const float* s3b   = (const float*)d_in[12];
    const float* Wseed = (const float*)d_in[13];
    const float* Ww    = (const float*)d_in[14];
    const float* Wpred = (const float*)d_in[15];
    const float* Wnv   = (const float*)d_in[16];
    const float* Wnb   = (const float*)d_in[17];
    const float* Wdel  = (const float*)d_in[18];
    const float* pmst  = (const float*)d_in[19];
    const float* emK   = (const float*)d_in[20];
    const float* emV   = (const float*)d_in[21];
    const float* lng   = (const float*)d_in[22];
    const float* lnb   = (const float*)d_in[23];
    float* out = (float*)d_out;

    float *X,*H,*bZ,*bA,*S,*seed,*wc,*pms,*dpm,*q,*sim;
    float *wnv,*smg,*nvs,*wiv,*kiv,*auxp;
    unsigned *pemb,*pwdel,*plno,*pS,*pwc,*pemK,*pemV,*pq,*psim;
    cudaGetSymbolAddress((void**)&X, g_X);
    cudaGetSymbolAddress((void**)&H, g_H);
    cudaGetSymbolAddress((void**)&bZ, g_bufZ);
    cudaGetSymbolAddress((void**)&bA, g_bufA);
    cudaGetSymbolAddress((void**)&S, g_surp);
    cudaGetSymbolAddress((void**)&seed, g_seed);
    cudaGetSymbolAddress((void**)&wc, g_wc);
    cudaGetSymbolAddress((void**)&pms, g_pms);
    cudaGetSymbolAddress((void**)&dpm, g_dpm);
    cudaGetSymbolAddress((void**)&q, g_q);
    cudaGetSymbolAddress((void**)&sim, g_sim);
    cudaGetSymbolAddress((void**)&wnv, g_wnv);
    cudaGetSymbolAddress((void**)&smg, g_smg);
    cudaGetSymbolAddress((void**)&nvs, g_nvs);
    cudaGetSymbolAddress((void**)&wiv, g_wiv);
    cudaGetSymbolAddress((void**)&kiv, g_kiv);
    cudaGetSymbolAddress((void**)&auxp, g_aux);
    cudaGetSymbolAddress((void**)&pemb, p_emb);
    cudaGetSymbolAddress((void**)&pwdel, p_wdel);
    cudaGetSymbolAddress((void**)&plno, p_lno);
    cudaGetSymbolAddress((void**)&pS, p_S);
    cudaGetSymbolAddress((void**)&pwc, p_wc);
    cudaGetSymbolAddress((void**)&pemK, p_emK);
    cudaGetSymbolAddress((void**)&pemV, p_emV);
    cudaGetSymbolAddress((void**)&pq, p_q);
    cudaGetSymbolAddress((void**)&psim, p_sim);

    const long long sND = (long long)SEQ*DM;
    const long long sMD = (long long)MS*DM;
    const long long sNM = (long long)SEQ*MS;
    const int GSM = 61440;

    cudaFuncSetAttribute(hgemm_k<true>,  cudaFuncAttributeMaxDynamicSharedMemorySize, GSM);
    cudaFuncSetAttribute(hgemm_k<false>, cudaFuncAttributeMaxDynamicSharedMemorySize, GSM);

    // pack constants
    pack_k<<<2048,256>>>(emb, pemb, (long long)VOC*DM/4);
    pack_k<<<1024,256>>>(Wdel, pwdel, (long long)NBK*DM*DM/4);
    pack_k<<<256,256>>>(emK, pemK, (long long)BSZ*NBK*MS*DM/4);
    pack_k<<<256,256>>>(emV, pemV, (long long)BSZ*NBK*MS*DM/4);

    embed_k<<<NR,256>>>(ids, emb, pos, X, H);

    for (int l=0;l<2;l++){
        lnproj_k<<<dim3(CC,NR/32),256>>>(H, s1Win+l*CC*DC*EE, s1Wg+l*CC*DC*EE,
                                         s1g+l*DC, s1b+l*DC, bZ, bA);
        scan_k<<<32,256>>>(bZ, bA);
        outproj_k<<<dim3(CC,NR/16),256>>>(bZ, s1Wo+l*CC*EE*DC, H);
    }

    pcm_k<<<dim3(CC,NR/32),256>>>(H, X, Wpred, S, auxp);
    seedw_k<<<dim3(CC,NR/32),256>>>(H, Wseed, Ww, seed, wc, pwc);
    rowstat_k<<<NR,256>>>(S, wc, H, Wnv, Wnb, smg, wiv, wnv);
    knorm_k<<<BSZ*NBK*MS,256>>>(emK, kiv);

    // similarity: w_cand @ em_K^T per (s,b)
    hgemm_k<true><<<dim3(1,SEQ/128,BSZ*NBK),256,GSM>>>(pwc, pemK, sim, (unsigned*)0,
        SEQ, MS, DM, DM, DM, MS, sND, sMD, sNM, NBK, 1.f);
    novel_k<<<NR,256>>>(sim, wnv, smg, wiv, kiv, nvs);
    cem_k<<<NR,256>>>(nvs, wc, bZ);
    cumsum_k<<<16,256>>>(bZ);

    // procedural memory: packed cumsum(surp) then 8 batched GEMMs vs W_delta
    cumsum_pack_k<<<16,256>>>(S, pS);
    hgemm_k<false><<<dim3(DM/128,NR/128,NBK),256,GSM>>>(pS, pwdel, dpm, (unsigned*)0,
        NR, DM, DM, DM, DM, DM, 0, (long long)DM*DM, (long long)NR*DM, NBK, 1.f);
    pmsum_k<<<NR,256>>>(dpm, pmst, pms);

    // trail attention
    qinit_k<<<8192,256>>>(seed, pq);
    for (int t=0;t<4;t++){
        hgemm_k<true><<<dim3(1,SEQ/128,BSZ*NBK),256,GSM>>>(pq, pemK, sim, (unsigned*)0,
            SEQ, MS, DM, DM, DM, MS, sND, sMD, sNM, 1, 1.f);
        softmax_k<<<BSZ*NBK*SEQ/8,256>>>(sim, psim);
        hgemm_k<false><<<dim3(DM/128,SEQ/128,BSZ*NBK),256,GSM>>>(psim, pemV, q, pq,
            SEQ, DM, MS, MS, DM, DM, sNM, sMD, sND, 1, 1.f);
    }

    integrate_k<<<NR,256>>>(H, pms, q, bZ, X);

    for (int l=0;l<2;l++){
        lnproj_k<<<dim3(CC,NR/32),256>>>(X, s3Win+l*CC*DC*EE, s3Wg+l*CC*DC*EE,
                                         s3g+l*DC, s3b+l*DC, bZ, bA);
        scan_k<<<32,256>>>(bZ, bA);
        outproj_k<<<dim3(CC,NR/16),256>>>(bZ, s3Wo+l*CC*EE*DC, X);
    }

    finalln_k<<<NR,256>>>(X, lng, lnb, plno);

    // logits: lno [4096,1024] @ emb^T [1024,32000]
    hgemm_k<true><<<dim3(VOC/128,NR/128,1),256,GSM>>>(plno, pemb, out, (unsigned*)0,
        NR, VOC, DM, DM, DM, VOC, 0, 0, 0, 1, 1.f);

    if ((long long)out_size > LOGN)
        auxfin_k<<<1,256>>>(auxp, out);
}